// round 11
// baseline (speedup 1.0000x reference)
#include <cuda_runtime.h>
#include <math.h>
#include <stdint.h>

#define BN 65536      // batch
#define DD 128        // dim
#define NS 16         // slots
#define NA 4096       // agents
#define EPSN 1e-12f
#define SCALEF 0.08838834764831845f   // 1/sqrt(128)
#define FULLM 0xffffffffu

// ---------------- scratch (static device memory; no runtime allocation) ----
__device__ float g_pqr[BN*DD];    // queries @ Wq^T + bq
__device__ float g_pqw[BN*DD];    // write_queries @ Wq^T + bq
__device__ float g_el[BN*DD];     // write_queries @ We^T + be   (pre-sigmoid)
__device__ float g_al[BN*DD];     // write_queries @ Wa^T + ba   (pre-tanh)
__device__ float g_read[BN*DD];   // attention read vectors
__device__ float g_inten[BN];     // sigmoid(wq @ Wg^T + bg)
__device__ float g_ww[BN*NS];     // write softmax weights
__device__ int   g_counts[NA];
__device__ int   g_offsets[NA];
__device__ int   g_cursor[NA];
__device__ int   g_bucket[BN];

// ---------------- tiny bookkeeping kernels ----------------------------------
__global__ void k_zero() {
    int t = blockIdx.x * blockDim.x + threadIdx.x;
    if (t < NA) { g_counts[t] = 0; g_cursor[t] = 0; }
}
__global__ void k_hist(const int* __restrict__ idx) {
    int r = blockIdx.x * blockDim.x + threadIdx.x;
    if (r < BN) atomicAdd(&g_counts[idx[r]], 1);
}

// ---------------- exclusive scan of counts (4096), 1 block -----------------
__global__ void k_scan() {
    __shared__ int wsum[32];
    const int t = threadIdx.x;
    int v[4];
    #pragma unroll
    for (int i = 0; i < 4; i++) v[i] = g_counts[t * 4 + i];
    int sum = v[0] + v[1] + v[2] + v[3];
    const int lane = t & 31, w = t >> 5;
    int sc = sum;
    #pragma unroll
    for (int o = 1; o < 32; o <<= 1) {
        int n = __shfl_up_sync(FULLM, sc, o);
        if (lane >= o) sc += n;
    }
    if (lane == 31) wsum[w] = sc;
    __syncthreads();
    if (w == 0) {
        int ws = wsum[lane];
        #pragma unroll
        for (int o = 1; o < 32; o <<= 1) {
            int n = __shfl_up_sync(FULLM, ws, o);
            if (lane >= o) ws += n;
        }
        wsum[lane] = ws;
    }
    __syncthreads();
    int base = (w > 0 ? wsum[w - 1] : 0) + sc - sum;
    #pragma unroll
    for (int i = 0; i < 4; i++) { g_offsets[t * 4 + i] = base; base += v[i]; }
}

// ---------------- bucket scatter --------------------------------------------
__global__ void k_scatter(const int* __restrict__ idx) {
    int r = blockIdx.x * blockDim.x + threadIdx.x;
    if (r < BN) {
        int a = idx[r];
        int p = atomicAdd(&g_cursor[a], 1);
        g_bucket[g_offsets[a] + p] = r;
    }
}

// ======================= tf32 tensor-core GEMM machinery ====================
#define LDK 68          // 64 k-floats + 4 pad (272B rows, 16B aligned)

__device__ __forceinline__ uint32_t f2tf32(float f) {
    uint32_t u;
    asm("cvt.rna.tf32.f32 %0, %1;" : "=r"(u) : "f"(f));
    return u;
}
__device__ __forceinline__ void ldsm4(uint32_t* r, uint32_t addr) {
    asm volatile("ldmatrix.sync.aligned.m8n8.x4.shared.b16 {%0,%1,%2,%3}, [%4];"
                 : "=r"(r[0]), "=r"(r[1]), "=r"(r[2]), "=r"(r[3]) : "r"(addr));
}
__device__ __forceinline__ void mma1688(float* c, const uint32_t* a, const uint32_t* b) {
    asm volatile("mma.sync.aligned.m16n8k8.row.col.f32.tf32.tf32.f32 "
                 "{%0,%1,%2,%3}, {%4,%5,%6,%7}, {%8,%9}, {%0,%1,%2,%3};"
                 : "+f"(c[0]), "+f"(c[1]), "+f"(c[2]), "+f"(c[3])
                 : "r"(a[0]), "r"(a[1]), "r"(a[2]), "r"(a[3]), "r"(b[0]), "r"(b[1]));
}

// ---------------- 2x2-way projection GEMM: C[B,128] = X @ W^T + b -----------
__global__ void __launch_bounds__(256, 2)
k_gemm_tc(const float* __restrict__ queries,
          const float* __restrict__ wqueries,
          const float* __restrict__ Wq, const float* __restrict__ bq,
          const float* __restrict__ We, const float* __restrict__ be,
          const float* __restrict__ Wa, const float* __restrict__ ba,
          int ybase)
{
    extern __shared__ float sh[];
    float* Xs = sh;               // [128][LDK]
    float* Ws = sh + 128 * LDK;   // [128][LDK]

    const float *X, *W, *bias;
    float* out;
    switch (blockIdx.y + ybase) {
        case 0:  X = queries;  W = Wq; bias = bq; out = g_pqr; break;
        case 1:  X = wqueries; W = Wq; bias = bq; out = g_pqw; break;
        case 2:  X = wqueries; W = We; bias = be; out = g_el;  break;
        default: X = wqueries; W = Wa; bias = ba; out = g_al;  break;
    }

    const int t = threadIdx.x;
    const int lane = t & 31, wid = t >> 5;
    const int wm = wid & 3;
    const int wn = wid >> 2;
    const int row0 = blockIdx.x * 128;

    float acc[2][8][4];
    #pragma unroll
    for (int i = 0; i < 2; i++)
        #pragma unroll
        for (int j = 0; j < 8; j++)
            #pragma unroll
            for (int k = 0; k < 4; k++) acc[i][j][k] = 0.f;

    const uint32_t xsBase = (uint32_t)__cvta_generic_to_shared(Xs);
    const uint32_t wsBase = (uint32_t)__cvta_generic_to_shared(Ws);
    const uint32_t aAddr = xsBase +
        (((wm * 32 + (lane & 15)) * LDK + ((lane >> 4) << 2)) << 2);
    const uint32_t bAddr = wsBase +
        (((wn * 64 + ((lane >> 4) << 3) + (lane & 7)) * LDK + (((lane >> 3) & 1) << 2)) << 2);

    for (int kc = 0; kc < 128; kc += 64) {
        #pragma unroll
        for (int i = t; i < 2048; i += 256) {
            int m = i >> 4, k4 = (i & 15) << 2;
            float4 v = *(const float4*)(X + (size_t)(row0 + m) * 128 + kc + k4);
            uint4 u;
            u.x = f2tf32(v.x); u.y = f2tf32(v.y); u.z = f2tf32(v.z); u.w = f2tf32(v.w);
            *(uint4*)(Xs + m * LDK + k4) = u;
        }
        #pragma unroll
        for (int i = t; i < 2048; i += 256) {
            int n = i >> 4, k4 = (i & 15) << 2;
            float4 v = *(const float4*)(W + (size_t)n * 128 + kc + k4);
            uint4 u;
            u.x = f2tf32(v.x); u.y = f2tf32(v.y); u.z = f2tf32(v.z); u.w = f2tf32(v.w);
            *(uint4*)(Ws + n * LDK + k4) = u;
        }
        __syncthreads();

        #pragma unroll
        for (int ks = 0; ks < 64; ks += 8) {
            uint32_t a[2][4];
            ldsm4(a[0], aAddr + (ks << 2));
            ldsm4(a[1], aAddr + ((16 * LDK + ks) << 2));
            uint32_t b[4][4];
            #pragma unroll
            for (int p = 0; p < 4; p++)
                ldsm4(b[p], bAddr + ((p * 16 * LDK + ks) << 2));
            #pragma unroll
            for (int mi = 0; mi < 2; mi++)
                #pragma unroll
                for (int p = 0; p < 4; p++) {
                    mma1688(acc[mi][p * 2 + 0], a[mi], &b[p][0]);
                    mma1688(acc[mi][p * 2 + 1], a[mi], &b[p][2]);
                }
        }
        __syncthreads();
    }

    const int cbase = wn * 64 + (lane & 3) * 2;
    const int rbase = row0 + wm * 32 + (lane >> 2);
    #pragma unroll
    for (int nj = 0; nj < 8; nj++) {
        int col = cbase + nj * 8;
        float b0 = bias[col], b1 = bias[col + 1];
        #pragma unroll
        for (int mi = 0; mi < 2; mi++) {
            float* c = acc[mi][nj];
            int r = rbase + mi * 16;
            *(float2*)(out + (size_t)r * 128 + col) = make_float2(c[0] + b0, c[1] + b1);
            *(float2*)(out + (size_t)(r + 8) * 128 + col) = make_float2(c[2] + b0, c[3] + b1);
        }
    }
}

// ---------------- fuse GEMM: outf = LN(gelu(g_read @ Wf^T + bf))*g + b ------
__global__ void __launch_bounds__(256, 2)
k_fuse(const float* __restrict__ Wf, const float* __restrict__ bf,
       const float* __restrict__ lng, const float* __restrict__ lnb,
       float* __restrict__ outf)
{
    extern __shared__ float sh[];
    float* Xs = sh;
    float* Ws = sh + 128 * LDK;

    const int t = threadIdx.x;
    const int lane = t & 31, wid = t >> 5;
    const int wm = wid & 3;
    const int wn = wid >> 2;
    const int row0 = blockIdx.x * 128;

    float acc[2][8][4];
    #pragma unroll
    for (int i = 0; i < 2; i++)
        #pragma unroll
        for (int j = 0; j < 8; j++)
            #pragma unroll
            for (int k = 0; k < 4; k++) acc[i][j][k] = 0.f;

    const uint32_t xsBase = (uint32_t)__cvta_generic_to_shared(Xs);
    const uint32_t wsBase = (uint32_t)__cvta_generic_to_shared(Ws);
    const uint32_t aAddr = xsBase +
        (((wm * 32 + (lane & 15)) * LDK + ((lane >> 4) << 2)) << 2);
    const uint32_t bAddr = wsBase +
        (((wn * 64 + ((lane >> 4) << 3) + (lane & 7)) * LDK + (((lane >> 3) & 1) << 2)) << 2);

    for (int kc = 0; kc < 128; kc += 64) {
        #pragma unroll
        for (int i = t; i < 2048; i += 256) {
            int m = i >> 4, k4 = (i & 15) << 2;
            float4 v = *(const float4*)(g_read + (size_t)(row0 + m) * 128 + kc + k4);
            uint4 u;
            u.x = f2tf32(v.x); u.y = f2tf32(v.y); u.z = f2tf32(v.z); u.w = f2tf32(v.w);
            *(uint4*)(Xs + m * LDK + k4) = u;
        }
        #pragma unroll
        for (int i = t; i < 2048; i += 256) {
            int n = i >> 4, k4 = (i & 15) << 2;
            float4 v = *(const float4*)(Wf + (size_t)n * 128 + kc + k4);
            uint4 u;
            u.x = f2tf32(v.x); u.y = f2tf32(v.y); u.z = f2tf32(v.z); u.w = f2tf32(v.w);
            *(uint4*)(Ws + n * LDK + k4) = u;
        }
        __syncthreads();

        #pragma unroll
        for (int ks = 0; ks < 64; ks += 8) {
            uint32_t a[2][4];
            ldsm4(a[0], aAddr + (ks << 2));
            ldsm4(a[1], aAddr + ((16 * LDK + ks) << 2));
            uint32_t b[4][4];
            #pragma unroll
            for (int p = 0; p < 4; p++)
                ldsm4(b[p], bAddr + ((p * 16 * LDK + ks) << 2));
            #pragma unroll
            for (int mi = 0; mi < 2; mi++)
                #pragma unroll
                for (int p = 0; p < 4; p++) {
                    mma1688(acc[mi][p * 2 + 0], a[mi], &b[p][0]);
                    mma1688(acc[mi][p * 2 + 1], a[mi], &b[p][2]);
                }
        }
        __syncthreads();
    }

    const float iSQ2 = 0.7071067811865476f;
    const int cbase = wn * 64 + (lane & 3) * 2;
    float sum[4] = {0.f, 0.f, 0.f, 0.f};
    float sq[4]  = {0.f, 0.f, 0.f, 0.f};

    #pragma unroll
    for (int nj = 0; nj < 8; nj++) {
        int col = cbase + nj * 8;
        float b0 = bf[col], b1 = bf[col + 1];
        #pragma unroll
        for (int mi = 0; mi < 2; mi++) {
            float* c = acc[mi][nj];
            #pragma unroll
            for (int q = 0; q < 4; q++) {
                float v = c[q] + ((q & 1) ? b1 : b0);
                v = 0.5f * v * (1.f + erff(v * iSQ2));
                c[q] = v;
                int ridx = mi * 2 + (q >> 1);
                sum[ridx] += v;
                sq[ridx] = fmaf(v, v, sq[ridx]);
            }
        }
    }
    #pragma unroll
    for (int o = 1; o <= 2; o <<= 1)
        #pragma unroll
        for (int ridx = 0; ridx < 4; ridx++) {
            sum[ridx] += __shfl_xor_sync(FULLM, sum[ridx], o);
            sq[ridx]  += __shfl_xor_sync(FULLM, sq[ridx], o);
        }

    float2* sums = (float2*)sh;    // [128 local rows][2 wn] {sum, sq}
    if ((lane & 3) == 0) {
        #pragma unroll
        for (int ridx = 0; ridx < 4; ridx++) {
            int lr = wm * 32 + (lane >> 2) + (ridx >> 1) * 16 + (ridx & 1) * 8;
            sums[lr * 2 + wn] = make_float2(sum[ridx], sq[ridx]);
        }
    }
    __syncthreads();

    #pragma unroll
    for (int mi = 0; mi < 2; mi++) {
        #pragma unroll
        for (int h = 0; h < 2; h++) {
            int lr = wm * 32 + (lane >> 2) + mi * 16 + h * 8;
            float2 p0 = sums[lr * 2 + 0];
            float2 p1 = sums[lr * 2 + 1];
            float mu = (p0.x + p1.x) * (1.f / 128.f);
            float var = (p0.y + p1.y) * (1.f / 128.f) - mu * mu;
            float rstd = rsqrtf(var + 1e-5f);
            int r = row0 + lr;
            #pragma unroll
            for (int nj = 0; nj < 8; nj++) {
                int col = cbase + nj * 8;
                float v0 = (acc[mi][nj][h * 2 + 0] - mu) * rstd * lng[col] + lnb[col];
                float v1 = (acc[mi][nj][h * 2 + 1] - mu) * rstd * lng[col + 1] + lnb[col + 1];
                *(float2*)(outf + (size_t)r * 128 + col) = make_float2(v0, v1);
            }
        }
    }
}

// ---------------- paired warp reduction --------------------------------------
__device__ __forceinline__ float pairred(float a0, float a1, int lane) {
    float x = (lane < 16) ? a1 : a0;
    x = __shfl_xor_sync(FULLM, x, 16);
    float t = ((lane < 16) ? a0 : a1) + x;
    t += __shfl_xor_sync(FULLM, t, 8);
    t += __shfl_xor_sync(FULLM, t, 4);
    t += __shfl_xor_sync(FULLM, t, 2);
    t += __shfl_xor_sync(FULLM, t, 1);
    return t;
}

// ---------------- by-agent fused attention (read+write) + intensity --------
// One block per agent: memory tile + slot norms staged in shared once; each
// warp walks the agent's bucket rows (mem served from LDS, not L2 gather).
__global__ void __launch_bounds__(256)
k_attn2(const float* __restrict__ mem,
        const float* __restrict__ wq, const float* __restrict__ Wg,
        const float* __restrict__ bg)
{
    __shared__ float sm[NS * 128];
    __shared__ float s_rmn[NS];
    const int a = blockIdx.x;
    const int cnt = g_counts[a];
    if (cnt == 0) return;
    const int t = threadIdx.x, lane = t & 31, wid = t >> 5;
    const int base = g_offsets[a];

    // stage agent tile (16 rows x 128 f32 = 512 float4)
    {
        const float4* msrc = (const float4*)(mem + (size_t)a * 2048);
        float4* mdst = (float4*)sm;
        mdst[t] = msrc[t];
        mdst[t + 256] = msrc[t + 256];
    }
    __syncthreads();

    // slot norms: warp w -> slots w (lanes<16) and w+8 (lanes>=16)
    {
        float4 v0 = ((const float4*)(sm + wid * 128))[lane];
        float4 v1 = ((const float4*)(sm + (wid + 8) * 128))[lane];
        float s0 = v0.x*v0.x + v0.y*v0.y + v0.z*v0.z + v0.w*v0.w;
        float s1 = v1.x*v1.x + v1.y*v1.y + v1.z*v1.z + v1.w*v1.w;
        float nn = pairred(s0, s1, lane);
        if (lane == 0)  s_rmn[wid]     = SCALEF / fmaxf(sqrtf(nn), EPSN);
        if (lane == 16) s_rmn[wid + 8] = SCALEF / fmaxf(sqrtf(nn), EPSN);
    }
    __syncthreads();

    const float rmn = s_rmn[lane & 15];
    const float4 gv = *(const float4*)(Wg + lane * 4);
    const float bg0 = bg[0];

    for (int i = wid; i < cnt; i += 8) {
        const int r = g_bucket[base + i];

        float4 qr = *(const float4*)(g_pqr + (size_t)r * 128 + lane * 4);
        float4 qw = *(const float4*)(g_pqw + (size_t)r * 128 + lane * 4);
        float nr0 = qr.x*qr.x + qr.y*qr.y + qr.z*qr.z + qr.w*qr.w;
        float nw0 = qw.x*qw.x + qw.y*qw.y + qw.z*qw.z + qw.w*qw.w;
        float nn = pairred(nr0, nw0, lane);        // <16: |qr|^2, >=16: |qw|^2
        float inv = 1.f / fmaxf(sqrtf(nn), EPSN);

        // intensity: sigmoid(wq . Wg + bg)
        {
            float4 x = *(const float4*)(wq + (size_t)r * 128 + lane * 4);
            float p = x.x * gv.x + x.y * gv.y + x.z * gv.z + x.w * gv.w;
            #pragma unroll
            for (int o = 16; o > 0; o >>= 1) p += __shfl_xor_sync(FULLM, p, o);
            if (lane == 0) g_inten[r] = 1.f / (1.f + __expf(-(p + bg0)));
        }

        float ax = 0.f, ay = 0.f, az = 0.f, aw2 = 0.f, lr = 0.f, lw = 0.f, myw = 0.f;
        #pragma unroll
        for (int j = 0; j < 8; j++) {
            const int s0 = 2 * j, s1 = 2 * j + 1;
            float4 m0 = ((const float4*)(sm + s0 * 128))[lane];
            float4 m1 = ((const float4*)(sm + s1 * 128))[lane];
            float p0 = m0.x*qr.x + m0.y*qr.y + m0.z*qr.z + m0.w*qr.w;
            float p1 = m0.x*qw.x + m0.y*qw.y + m0.z*qw.z + m0.w*qw.w;
            float p2 = m1.x*qr.x + m1.y*qr.y + m1.z*qr.z + m1.w*qr.w;
            float p3 = m1.x*qw.x + m1.y*qw.y + m1.z*qw.z + m1.w*qw.w;

            float x1 = (lane & 16) ? p0 : p1;
            x1 = __shfl_xor_sync(FULLM, x1, 16);
            float A = ((lane & 16) ? p1 : p0) + x1;
            float x2 = (lane & 16) ? p2 : p3;
            x2 = __shfl_xor_sync(FULLM, x2, 16);
            float Bv = ((lane & 16) ? p3 : p2) + x2;
            float x3 = (lane & 8) ? A : Bv;
            x3 = __shfl_xor_sync(FULLM, x3, 8);
            float C = ((lane & 8) ? Bv : A) + x3;      // octets: p0|p2|p1|p3
            C += __shfl_xor_sync(FULLM, C, 4);
            C += __shfl_xor_sync(FULLM, C, 2);
            C += __shfl_xor_sync(FULLM, C, 1);

            float rmnj = __shfl_sync(FULLM, rmn, s0 + ((lane >> 3) & 1));
            float e = __expf(C * inv * rmnj);
            float er0 = __shfl_sync(FULLM, e, 0);
            float er1 = __shfl_sync(FULLM, e, 8);
            float ew0 = __shfl_sync(FULLM, e, 16);
            float ew1 = __shfl_sync(FULLM, e, 24);
            lr += er0 + er1;
            lw += ew0 + ew1;
            ax  = fmaf(er0, m0.x, fmaf(er1, m1.x, ax));
            ay  = fmaf(er0, m0.y, fmaf(er1, m1.y, ay));
            az  = fmaf(er0, m0.z, fmaf(er1, m1.z, az));
            aw2 = fmaf(er0, m0.w, fmaf(er1, m1.w, aw2));
            if (lane == s0) myw = ew0;
            if (lane == s1) myw = ew1;
        }
        float invl = 1.f / lr;
        *(float4*)(g_read + (size_t)r * 128 + lane * 4) =
            make_float4(ax * invl, ay * invl, az * invl, aw2 * invl);
        if (lane < 16) g_ww[r * 16 + lane] = myw / lw;
    }
}

// ---------------- per-agent gather-reduce + memory update + l2norm ---------
__global__ void k_agent(const float* __restrict__ mem, float* __restrict__ outm)
{
    __shared__ float part[8][8];
    __shared__ float nsh[16];
    const int a = blockIdx.x;
    const int t = threadIdx.x;
    const int d = t & 127;
    const int sg = t >> 7;
    const float* mrow = mem + (size_t)a * 2048;
    float* orow = outm + (size_t)a * 2048;
    const int cnt = g_counts[a];
    if (cnt == 0) {
        #pragma unroll
        for (int k = 0; k < 8; k++)
            orow[(sg * 8 + k) * 128 + d] = mrow[(sg * 8 + k) * 128 + d];
        return;
    }
    const int base = g_offsets[a];
    float E[8], A[8];
    #pragma unroll
    for (int k = 0; k < 8; k++) { E[k] = 0.f; A[k] = 0.f; }

    for (int i = 0; i < cnt; i++) {
        int r = g_bucket[base + i];
        float eld = g_el[(size_t)r * 128 + d];
        float ald = g_al[(size_t)r * 128 + d];
        float itn = g_inten[r];
        float4 w0 = *(const float4*)(g_ww + r * 16 + sg * 8);
        float4 w1 = *(const float4*)(g_ww + r * 16 + sg * 8 + 4);
        float ei = itn / (1.f + __expf(-eld));
        float ai = itn * (1.f - 2.f / (__expf(2.f * ald) + 1.f));
        E[0] = fmaf(w0.x, ei, E[0]); A[0] = fmaf(w0.x, ai, A[0]);
        E[1] = fmaf(w0.y, ei, E[1]); A[1] = fmaf(w0.y, ai, A[1]);
        E[2] = fmaf(w0.z, ei, E[2]); A[2] = fmaf(w0.z, ai, A[2]);
        E[3] = fmaf(w0.w, ei, E[3]); A[3] = fmaf(w0.w, ai, A[3]);
        E[4] = fmaf(w1.x, ei, E[4]); A[4] = fmaf(w1.x, ai, A[4]);
        E[5] = fmaf(w1.y, ei, E[5]); A[5] = fmaf(w1.y, ai, A[5]);
        E[6] = fmaf(w1.z, ei, E[6]); A[6] = fmaf(w1.z, ai, A[6]);
        E[7] = fmaf(w1.w, ei, E[7]); A[7] = fmaf(w1.w, ai, A[7]);
    }

    float nv[8], p2[8];
    #pragma unroll
    for (int k = 0; k < 8; k++) {
        float m = mrow[(sg * 8 + k) * 128 + d];
        nv[k] = m * (1.f - E[k]) + A[k];
        p2[k] = nv[k] * nv[k];
    }
    #pragma unroll
    for (int o = 16; o > 0; o >>= 1) {
        #pragma unroll
        for (int k = 0; k < 8; k++) p2[k] += __shfl_xor_sync(FULLM, p2[k], o);
    }
    const int wp = t >> 5, lane = t & 31;
    if (lane == 0) {
        #pragma unroll
        for (int k = 0; k < 8; k++) part[wp][k] = p2[k];
    }
    __syncthreads();
    if (t < 16) {
        float n2 = part[(t >> 3) * 4 + 0][t & 7] + part[(t >> 3) * 4 + 1][t & 7]
                 + part[(t >> 3) * 4 + 2][t & 7] + part[(t >> 3) * 4 + 3][t & 7];
        nsh[t] = fmaxf(sqrtf(n2), EPSN);
    }
    __syncthreads();
    #pragma unroll
    for (int k = 0; k < 8; k++)
        orow[(sg * 8 + k) * 128 + d] = nv[k] / nsh[sg * 8 + k];
}

// ---------------- launch: fork-join graph ------------------------------------
//   main: (e0) gemmA (e1) -> [wait e2] attn2 (e3) -> [wait e2b] agent -> [wait e4]
//   s2:   [wait e0] zero -> hist -> scan -> scatter (e2) -> [wait e1] gemmB (e2b)
//   s3:   [wait e3] fuse (e4)
// NOTE: every side-stream chain MUST begin with a wait on an event recorded
// in the capturing stream (capture fork rule — round-10 failure).
extern "C" void kernel_launch(void* const* d_in, const int* in_sizes, int n_in,
                              void* d_out, int out_size)
{
    const float* queries  = (const float*)d_in[0];
    const float* wqueries = (const float*)d_in[1];
    const float* memory   = (const float*)d_in[2];
    const float* Wq  = (const float*)d_in[3];
    const float* bq  = (const float*)d_in[4];
    const float* We  = (const float*)d_in[5];
    const float* be  = (const float*)d_in[6];
    const float* Wa  = (const float*)d_in[7];
    const float* ba  = (const float*)d_in[8];
    const float* Wf  = (const float*)d_in[9];
    const float* bf  = (const float*)d_in[10];
    const float* lng = (const float*)d_in[11];
    const float* lnb = (const float*)d_in[12];
    const float* Wg  = (const float*)d_in[13];
    const float* bg  = (const float*)d_in[14];
    const int*   idx = (const int*)d_in[15];

    float* outf = (float*)d_out;                 // fused_read [B,128]
    float* outm = outf + (size_t)BN * DD;        // new_memory [4096,16,128]

    const int gemm_smem = 2 * 128 * LDK * 4;     // 69632

    static cudaStream_t s2 = nullptr, s3 = nullptr;
    static cudaEvent_t e0, e1, e2, e2b, e3, e4;
    if (s2 == nullptr) {
        cudaStreamCreateWithFlags(&s2, cudaStreamNonBlocking);
        cudaStreamCreateWithFlags(&s3, cudaStreamNonBlocking);
        cudaEventCreateWithFlags(&e0,  cudaEventDisableTiming);
        cudaEventCreateWithFlags(&e1,  cudaEventDisableTiming);
        cudaEventCreateWithFlags(&e2,  cudaEventDisableTiming);
        cudaEventCreateWithFlags(&e2b, cudaEventDisableTiming);
        cudaEventCreateWithFlags(&e3,  cudaEventDisableTiming);
        cudaEventCreateWithFlags(&e4,  cudaEventDisableTiming);
        cudaFuncSetAttribute(k_gemm_tc, cudaFuncAttributeMaxDynamicSharedMemorySize, gemm_smem);
        cudaFuncSetAttribute(k_fuse,    cudaFuncAttributeMaxDynamicSharedMemorySize, gemm_smem);
    }

    // fork point for the side chain (legal capture fork)
    cudaEventRecord(e0, (cudaStream_t)0);

    // side chain: bucket construction (independent of GEMMs)
    cudaStreamWaitEvent(s2, e0, 0);
    k_zero<<<16, 256, 0, s2>>>();
    k_hist<<<BN / 256, 256, 0, s2>>>(idx);
    k_scan<<<1, 1024, 0, s2>>>();
    k_scatter<<<BN / 256, 256, 0, s2>>>(idx);
    cudaEventRecord(e2, s2);

    // main: projections for attention
    k_gemm_tc<<<dim3(BN / 128, 2), 256, gemm_smem>>>(
        queries, wqueries, Wq, bq, We, be, Wa, ba, 0);             // pqr, pqw
    cudaEventRecord(e1, (cudaStream_t)0);

    // side: erase/add projections (needed only by k_agent)
    cudaStreamWaitEvent(s2, e1, 0);
    k_gemm_tc<<<dim3(BN / 128, 2), 256, gemm_smem, s2>>>(
        queries, wqueries, Wq, bq, We, be, Wa, ba, 2);             // el, al
    cudaEventRecord(e2b, s2);

    // main: by-agent attention
    cudaStreamWaitEvent((cudaStream_t)0, e2, 0);
    k_attn2<<<NA, 256>>>(memory, wqueries, Wg, bg);
    cudaEventRecord(e3, (cudaStream_t)0);

    // side: fuse (overlaps agent)
    cudaStreamWaitEvent(s3, e3, 0);
    k_fuse<<<BN / 128, 256, gemm_smem, s3>>>(Wf, bf, lng, lnb, outf);
    cudaEventRecord(e4, s3);

    // main: memory update
    cudaStreamWaitEvent((cudaStream_t)0, e2b, 0);
    k_agent<<<NA, 256>>>(memory, outm);
    cudaStreamWaitEvent((cudaStream_t)0, e4, 0);
}

// round 12
// speedup vs baseline: 1.1604x; 1.1604x over previous
#include <cuda_runtime.h>
#include <cuda_fp16.h>
#include <math.h>
#include <stdint.h>

#define BN 65536      // batch
#define DD 128        // dim
#define NS 16         // slots
#define NA 4096       // agents
#define EPSN 1e-12f
#define SCALEF 0.08838834764831845f   // 1/sqrt(128)
#define FULLM 0xffffffffu

// ---------------- scratch (static device memory; no runtime allocation) ----
__device__ float g_pqr[BN*DD];    // queries @ Wq^T + bq
__device__ float g_pqw[BN*DD];    // write_queries @ Wq^T + bq
__device__ float g_el[BN*DD];     // write_queries @ We^T + be   (pre-sigmoid)
__device__ float g_al[BN*DD];     // write_queries @ Wa^T + ba   (pre-tanh)
__device__ float g_read[BN*DD];   // attention read vectors
__device__ float g_inten[BN];     // sigmoid(wq @ Wg^T + bg)
__device__ float g_ww[BN*NS];     // write softmax weights
__device__ float g_rmn[NA*NS];    // SCALEF / max(||mem[a,s]||, eps)
__device__ int   g_counts[NA];
__device__ int   g_offsets[NA];
__device__ int   g_cursor[NA];
__device__ int   g_bucket[BN];

// ---------------- per-(agent,slot) reciprocal norms + zero counts ----------
__global__ void k_mnorm(const float* __restrict__ mem) {
    int gt = blockIdx.x * blockDim.x + threadIdx.x;
    if (gt < NA) { g_counts[gt] = 0; g_cursor[gt] = 0; }
    int w = gt >> 5;   // 0..65535 slot rows
    int lane = threadIdx.x & 31;
    float4 v = *(const float4*)(mem + (size_t)w * 128 + lane * 4);
    float s = v.x*v.x + v.y*v.y + v.z*v.z + v.w*v.w;
    #pragma unroll
    for (int o = 16; o > 0; o >>= 1) s += __shfl_xor_sync(FULLM, s, o);
    if (lane == 0) g_rmn[w] = SCALEF / fmaxf(sqrtf(s), EPSN);
}

// ======================= fp16 tensor-core GEMM machinery ====================
// fp16 mantissa == tf32 mantissa (10 bits) -> same accuracy, 2x HMMA rate.
#define LDH 136   // halves per row: 128 + 8 pad (272B rows; 17x16B -> ldsm conflict-free)

__device__ __forceinline__ void ldsm4(uint32_t* r, uint32_t addr) {
    asm volatile("ldmatrix.sync.aligned.m8n8.x4.shared.b16 {%0,%1,%2,%3}, [%4];"
                 : "=r"(r[0]), "=r"(r[1]), "=r"(r[2]), "=r"(r[3]) : "r"(addr));
}
__device__ __forceinline__ void mma16816(float* c, const uint32_t* a, const uint32_t* b) {
    asm volatile("mma.sync.aligned.m16n8k16.row.col.f32.f16.f16.f32 "
                 "{%0,%1,%2,%3}, {%4,%5,%6,%7}, {%8,%9}, {%0,%1,%2,%3};"
                 : "+f"(c[0]), "+f"(c[1]), "+f"(c[2]), "+f"(c[3])
                 : "r"(a[0]), "r"(a[1]), "r"(a[2]), "r"(a[3]), "r"(b[0]), "r"(b[1]));
}
__device__ __forceinline__ uint2 f4_to_h4(float4 v) {
    __half2 h0 = __floats2half2_rn(v.x, v.y);
    __half2 h1 = __floats2half2_rn(v.z, v.w);
    uint2 u;
    u.x = *(uint32_t*)&h0;
    u.y = *(uint32_t*)&h1;
    return u;
}

// ---------------- 2x2-way projection GEMM: C[B,128] = X @ W^T + b -----------
// Full K=128 staged once as fp16 (one __syncthreads, 8 straight k16 steps).
__global__ void __launch_bounds__(256, 2)
k_gemm_h(const float* __restrict__ queries,
         const float* __restrict__ wqueries,
         const float* __restrict__ Wq, const float* __restrict__ bq,
         const float* __restrict__ We, const float* __restrict__ be,
         const float* __restrict__ Wa, const float* __restrict__ ba,
         int ybase)
{
    extern __shared__ char smraw[];
    __half* Xs = (__half*)smraw;            // [128][LDH]
    __half* Ws = Xs + 128 * LDH;            // [128][LDH]

    const float *X, *W, *bias;
    float* out;
    switch (blockIdx.y + ybase) {
        case 0:  X = queries;  W = Wq; bias = bq; out = g_pqr; break;
        case 1:  X = wqueries; W = Wq; bias = bq; out = g_pqw; break;
        case 2:  X = wqueries; W = We; bias = be; out = g_el;  break;
        default: X = wqueries; W = Wa; bias = ba; out = g_al;  break;
    }

    const int t = threadIdx.x;
    const int lane = t & 31, wid = t >> 5;
    const int wm = wid & 3;        // 4 warp-rows -> 32 M each
    const int wn = wid >> 2;       // 2 warp-cols -> 64 N each
    const int row0 = blockIdx.x * 128;

    // stage X and W (f32 -> f16), full K
    #pragma unroll
    for (int i = t; i < 4096; i += 256) {          // 128 rows x 32 float4
        int m = i >> 5, k4 = (i & 31) << 2;
        *(uint2*)(Xs + m * LDH + k4) =
            f4_to_h4(*(const float4*)(X + (size_t)(row0 + m) * 128 + k4));
    }
    #pragma unroll
    for (int i = t; i < 4096; i += 256) {
        int n = i >> 5, k4 = (i & 31) << 2;
        *(uint2*)(Ws + n * LDH + k4) =
            f4_to_h4(*(const float4*)(W + (size_t)n * 128 + k4));
    }
    __syncthreads();

    float acc[2][8][4];
    #pragma unroll
    for (int i = 0; i < 2; i++)
        #pragma unroll
        for (int j = 0; j < 8; j++)
            #pragma unroll
            for (int k = 0; k < 4; k++) acc[i][j][k] = 0.f;

    const uint32_t xsBase = (uint32_t)__cvta_generic_to_shared(Xs);
    const uint32_t wsBase = (uint32_t)__cvta_generic_to_shared(Ws);
    // A frag: rows (lane&15), k-half (lane>>4)*8 halves
    const uint32_t aAddr = xsBase +
        (((wm * 32 + (lane & 15)) * LDH + ((lane >> 4) << 3)) << 1);
    // B frag x4: two n8 tiles x two k-halves
    const uint32_t bAddr = wsBase +
        (((wn * 64 + ((lane >> 4) << 3) + (lane & 7)) * LDH + (((lane >> 3) & 1) << 3)) << 1);

    #pragma unroll
    for (int ks = 0; ks < 128; ks += 16) {
        uint32_t a[2][4];
        ldsm4(a[0], aAddr + (ks << 1));
        ldsm4(a[1], aAddr + ((16 * LDH + ks) << 1));
        uint32_t b[4][4];
        #pragma unroll
        for (int p = 0; p < 4; p++)
            ldsm4(b[p], bAddr + ((p * 16 * LDH + ks) << 1));
        #pragma unroll
        for (int mi = 0; mi < 2; mi++)
            #pragma unroll
            for (int p = 0; p < 4; p++) {
                mma16816(acc[mi][p * 2 + 0], a[mi], &b[p][0]);
                mma16816(acc[mi][p * 2 + 1], a[mi], &b[p][2]);
            }
    }

    const int cbase = wn * 64 + (lane & 3) * 2;
    const int rbase = row0 + wm * 32 + (lane >> 2);
    #pragma unroll
    for (int nj = 0; nj < 8; nj++) {
        int col = cbase + nj * 8;
        float b0 = bias[col], b1 = bias[col + 1];
        #pragma unroll
        for (int mi = 0; mi < 2; mi++) {
            float* c = acc[mi][nj];
            int r = rbase + mi * 16;
            *(float2*)(out + (size_t)r * 128 + col) = make_float2(c[0] + b0, c[1] + b1);
            *(float2*)(out + (size_t)(r + 8) * 128 + col) = make_float2(c[2] + b0, c[3] + b1);
        }
    }
}

// ---------------- fuse GEMM: outf = LN(gelu(g_read @ Wf^T + bf))*g + b ------
__global__ void __launch_bounds__(256, 2)
k_fuse_h(const float* __restrict__ Wf, const float* __restrict__ bf,
         const float* __restrict__ lng, const float* __restrict__ lnb,
         float* __restrict__ outf)
{
    extern __shared__ char smraw[];
    __half* Xs = (__half*)smraw;
    __half* Ws = Xs + 128 * LDH;

    const int t = threadIdx.x;
    const int lane = t & 31, wid = t >> 5;
    const int wm = wid & 3;
    const int wn = wid >> 2;
    const int row0 = blockIdx.x * 128;

    #pragma unroll
    for (int i = t; i < 4096; i += 256) {
        int m = i >> 5, k4 = (i & 31) << 2;
        *(uint2*)(Xs + m * LDH + k4) =
            f4_to_h4(*(const float4*)(g_read + (size_t)(row0 + m) * 128 + k4));
    }
    #pragma unroll
    for (int i = t; i < 4096; i += 256) {
        int n = i >> 5, k4 = (i & 31) << 2;
        *(uint2*)(Ws + n * LDH + k4) =
            f4_to_h4(*(const float4*)(Wf + (size_t)n * 128 + k4));
    }
    __syncthreads();

    float acc[2][8][4];
    #pragma unroll
    for (int i = 0; i < 2; i++)
        #pragma unroll
        for (int j = 0; j < 8; j++)
            #pragma unroll
            for (int k = 0; k < 4; k++) acc[i][j][k] = 0.f;

    const uint32_t xsBase = (uint32_t)__cvta_generic_to_shared(Xs);
    const uint32_t wsBase = (uint32_t)__cvta_generic_to_shared(Ws);
    const uint32_t aAddr = xsBase +
        (((wm * 32 + (lane & 15)) * LDH + ((lane >> 4) << 3)) << 1);
    const uint32_t bAddr = wsBase +
        (((wn * 64 + ((lane >> 4) << 3) + (lane & 7)) * LDH + (((lane >> 3) & 1) << 3)) << 1);

    #pragma unroll
    for (int ks = 0; ks < 128; ks += 16) {
        uint32_t a[2][4];
        ldsm4(a[0], aAddr + (ks << 1));
        ldsm4(a[1], aAddr + ((16 * LDH + ks) << 1));
        uint32_t b[4][4];
        #pragma unroll
        for (int p = 0; p < 4; p++)
            ldsm4(b[p], bAddr + ((p * 16 * LDH + ks) << 1));
        #pragma unroll
        for (int mi = 0; mi < 2; mi++)
            #pragma unroll
            for (int p = 0; p < 4; p++) {
                mma16816(acc[mi][p * 2 + 0], a[mi], &b[p][0]);
                mma16816(acc[mi][p * 2 + 1], a[mi], &b[p][2]);
            }
    }
    __syncthreads();   // before reusing smem for LN partials

    // ---- epilogue: bias + exact gelu, per-row LN via cross-warp partials ----
    const float iSQ2 = 0.7071067811865476f;
    const int cbase = wn * 64 + (lane & 3) * 2;
    float sum[4] = {0.f, 0.f, 0.f, 0.f};
    float sq[4]  = {0.f, 0.f, 0.f, 0.f};

    #pragma unroll
    for (int nj = 0; nj < 8; nj++) {
        int col = cbase + nj * 8;
        float b0 = bf[col], b1 = bf[col + 1];
        #pragma unroll
        for (int mi = 0; mi < 2; mi++) {
            float* c = acc[mi][nj];
            #pragma unroll
            for (int q = 0; q < 4; q++) {
                float v = c[q] + ((q & 1) ? b1 : b0);
                v = 0.5f * v * (1.f + erff(v * iSQ2));
                c[q] = v;
                int ridx = mi * 2 + (q >> 1);
                sum[ridx] += v;
                sq[ridx] = fmaf(v, v, sq[ridx]);
            }
        }
    }
    #pragma unroll
    for (int o = 1; o <= 2; o <<= 1)
        #pragma unroll
        for (int ridx = 0; ridx < 4; ridx++) {
            sum[ridx] += __shfl_xor_sync(FULLM, sum[ridx], o);
            sq[ridx]  += __shfl_xor_sync(FULLM, sq[ridx], o);
        }

    float2* sums = (float2*)smraw;    // [128 local rows][2 wn] {sum, sq}
    if ((lane & 3) == 0) {
        #pragma unroll
        for (int ridx = 0; ridx < 4; ridx++) {
            int lr = wm * 32 + (lane >> 2) + (ridx >> 1) * 16 + (ridx & 1) * 8;
            sums[lr * 2 + wn] = make_float2(sum[ridx], sq[ridx]);
        }
    }
    __syncthreads();

    #pragma unroll
    for (int mi = 0; mi < 2; mi++) {
        #pragma unroll
        for (int h = 0; h < 2; h++) {
            int lr = wm * 32 + (lane >> 2) + mi * 16 + h * 8;
            float2 p0 = sums[lr * 2 + 0];
            float2 p1 = sums[lr * 2 + 1];
            float mu = (p0.x + p1.x) * (1.f / 128.f);
            float var = (p0.y + p1.y) * (1.f / 128.f) - mu * mu;
            float rstd = rsqrtf(var + 1e-5f);
            int r = row0 + lr;
            #pragma unroll
            for (int nj = 0; nj < 8; nj++) {
                int col = cbase + nj * 8;
                float v0 = (acc[mi][nj][h * 2 + 0] - mu) * rstd * lng[col] + lnb[col];
                float v1 = (acc[mi][nj][h * 2 + 1] - mu) * rstd * lng[col + 1] + lnb[col + 1];
                *(float2*)(outf + (size_t)r * 128 + col) = make_float2(v0, v1);
            }
        }
    }
}

// ---------------- exclusive scan of counts (4096), 1 block -----------------
__global__ void k_scan() {
    __shared__ int wsum[32];
    const int t = threadIdx.x;
    int v[4];
    #pragma unroll
    for (int i = 0; i < 4; i++) v[i] = g_counts[t * 4 + i];
    int sum = v[0] + v[1] + v[2] + v[3];
    const int lane = t & 31, w = t >> 5;
    int sc = sum;
    #pragma unroll
    for (int o = 1; o < 32; o <<= 1) {
        int n = __shfl_up_sync(FULLM, sc, o);
        if (lane >= o) sc += n;
    }
    if (lane == 31) wsum[w] = sc;
    __syncthreads();
    if (w == 0) {
        int ws = wsum[lane];
        #pragma unroll
        for (int o = 1; o < 32; o <<= 1) {
            int n = __shfl_up_sync(FULLM, ws, o);
            if (lane >= o) ws += n;
        }
        wsum[lane] = ws;
    }
    __syncthreads();
    int base = (w > 0 ? wsum[w - 1] : 0) + sc - sum;
    #pragma unroll
    for (int i = 0; i < 4; i++) { g_offsets[t * 4 + i] = base; base += v[i]; }
}

// ---------------- bucket scatter --------------------------------------------
__global__ void k_scatter(const int* __restrict__ idx) {
    int r = blockIdx.x * blockDim.x + threadIdx.x;
    if (r < BN) {
        int a = idx[r];
        int p = atomicAdd(&g_cursor[a], 1);
        g_bucket[g_offsets[a] + p] = r;
    }
}

// ---------------- paired warp reduction (for query norms) -------------------
__device__ __forceinline__ float pairred(float a0, float a1, int lane) {
    float x = (lane < 16) ? a1 : a0;
    x = __shfl_xor_sync(FULLM, x, 16);
    float t = ((lane < 16) ? a0 : a1) + x;
    t += __shfl_xor_sync(FULLM, t, 8);
    t += __shfl_xor_sync(FULLM, t, 4);
    t += __shfl_xor_sync(FULLM, t, 2);
    t += __shfl_xor_sync(FULLM, t, 1);
    return t;
}

// ---------------- fused attention (read+write) + intensity + histogram -----
__global__ void __launch_bounds__(256)
k_attn(const float* __restrict__ mem, const int* __restrict__ idx,
       const float* __restrict__ wq, const float* __restrict__ Wg,
       const float* __restrict__ bg)
{
    const int t = threadIdx.x, lane = t & 31;
    const int r = blockIdx.x * 8 + (t >> 5);
    const int a = idx[r];

    float4 qr = *(const float4*)(g_pqr + (size_t)r * 128 + lane * 4);
    float4 qw = *(const float4*)(g_pqw + (size_t)r * 128 + lane * 4);
    float nr0 = qr.x*qr.x + qr.y*qr.y + qr.z*qr.z + qr.w*qr.w;
    float nw0 = qw.x*qw.x + qw.y*qw.y + qw.z*qw.z + qw.w*qw.w;
    float nn = pairred(nr0, nw0, lane);        // lanes<16: |qr|^2, >=16: |qw|^2
    float inv = 1.f / fmaxf(sqrtf(nn), EPSN);

    // intensity: sigmoid(wq . Wg + bg) + agent histogram
    {
        float4 x = *(const float4*)(wq + (size_t)r * 128 + lane * 4);
        float4 g = *(const float4*)(Wg + lane * 4);
        float p = x.x * g.x + x.y * g.y + x.z * g.z + x.w * g.w;
        #pragma unroll
        for (int o = 16; o > 0; o >>= 1) p += __shfl_xor_sync(FULLM, p, o);
        if (lane == 0) {
            g_inten[r] = 1.f / (1.f + __expf(-(p + bg[0])));
            atomicAdd(&g_counts[a], 1);
        }
    }

    float rmn = g_rmn[a * 16 + (lane & 15)];   // reciprocal slot norms (pre-scaled)

    float ax = 0.f, ay = 0.f, az = 0.f, aw2 = 0.f, lr = 0.f, lw = 0.f, myw = 0.f;
    const float* mrow = mem + (size_t)a * 2048;
    #pragma unroll
    for (int j = 0; j < 8; j++) {
        const int s0 = 2 * j, s1 = 2 * j + 1;
        float4 m0 = *(const float4*)(mrow + s0 * 128 + lane * 4);
        float4 m1 = *(const float4*)(mrow + s1 * 128 + lane * 4);
        float p0 = m0.x*qr.x + m0.y*qr.y + m0.z*qr.z + m0.w*qr.w;   // m0.qr
        float p1 = m0.x*qw.x + m0.y*qw.y + m0.z*qw.z + m0.w*qw.w;   // m0.qw
        float p2 = m1.x*qr.x + m1.y*qr.y + m1.z*qr.z + m1.w*qr.w;   // m1.qr
        float p3 = m1.x*qw.x + m1.y*qw.y + m1.z*qw.z + m1.w*qw.w;   // m1.qw

        float x1 = (lane & 16) ? p0 : p1;
        x1 = __shfl_xor_sync(FULLM, x1, 16);
        float A = ((lane & 16) ? p1 : p0) + x1;
        float x2 = (lane & 16) ? p2 : p3;
        x2 = __shfl_xor_sync(FULLM, x2, 16);
        float Bv = ((lane & 16) ? p3 : p2) + x2;
        float x3 = (lane & 8) ? A : Bv;
        x3 = __shfl_xor_sync(FULLM, x3, 8);
        float C = ((lane & 8) ? Bv : A) + x3;      // octets: p0|p2|p1|p3
        C += __shfl_xor_sync(FULLM, C, 4);
        C += __shfl_xor_sync(FULLM, C, 2);
        C += __shfl_xor_sync(FULLM, C, 1);

        float rmnj = __shfl_sync(FULLM, rmn, s0 + ((lane >> 3) & 1));
        float e = __expf(C * inv * rmnj);          // one exp per thread
        float er0 = __shfl_sync(FULLM, e, 0);
        float er1 = __shfl_sync(FULLM, e, 8);
        float ew0 = __shfl_sync(FULLM, e, 16);
        float ew1 = __shfl_sync(FULLM, e, 24);
        lr += er0 + er1;
        lw += ew0 + ew1;
        ax  = fmaf(er0, m0.x, fmaf(er1, m1.x, ax));
        ay  = fmaf(er0, m0.y, fmaf(er1, m1.y, ay));
        az  = fmaf(er0, m0.z, fmaf(er1, m1.z, az));
        aw2 = fmaf(er0, m0.w, fmaf(er1, m1.w, aw2));
        if (lane == s0) myw = ew0;
        if (lane == s1) myw = ew1;
    }
    float invl = 1.f / lr;
    *(float4*)(g_read + (size_t)r * 128 + lane * 4) =
        make_float4(ax * invl, ay * invl, az * invl, aw2 * invl);
    if (lane < 16) g_ww[r * 16 + lane] = myw / lw;
}

// ---------------- per-agent gather-reduce + memory update + l2norm ---------
__global__ void k_agent(const float* __restrict__ mem, float* __restrict__ outm)
{
    __shared__ float part[8][8];
    __shared__ float nsh[16];
    const int a = blockIdx.x;
    const int t = threadIdx.x;
    const int d = t & 127;
    const int sg = t >> 7;
    const float* mrow = mem + (size_t)a * 2048;
    float* orow = outm + (size_t)a * 2048;
    const int cnt = g_counts[a];
    if (cnt == 0) {
        #pragma unroll
        for (int k = 0; k < 8; k++)
            orow[(sg * 8 + k) * 128 + d] = mrow[(sg * 8 + k) * 128 + d];
        return;
    }
    const int base = g_offsets[a];
    float E[8], A[8];
    #pragma unroll
    for (int k = 0; k < 8; k++) { E[k] = 0.f; A[k] = 0.f; }

    for (int i = 0; i < cnt; i++) {
        int r = g_bucket[base + i];
        float eld = g_el[(size_t)r * 128 + d];
        float ald = g_al[(size_t)r * 128 + d];
        float itn = g_inten[r];
        float4 w0 = *(const float4*)(g_ww + r * 16 + sg * 8);
        float4 w1 = *(const float4*)(g_ww + r * 16 + sg * 8 + 4);
        float ei = itn / (1.f + __expf(-eld));
        float ai = itn * (1.f - 2.f / (__expf(2.f * ald) + 1.f));
        E[0] = fmaf(w0.x, ei, E[0]); A[0] = fmaf(w0.x, ai, A[0]);
        E[1] = fmaf(w0.y, ei, E[1]); A[1] = fmaf(w0.y, ai, A[1]);
        E[2] = fmaf(w0.z, ei, E[2]); A[2] = fmaf(w0.z, ai, A[2]);
        E[3] = fmaf(w0.w, ei, E[3]); A[3] = fmaf(w0.w, ai, A[3]);
        E[4] = fmaf(w1.x, ei, E[4]); A[4] = fmaf(w1.x, ai, A[4]);
        E[5] = fmaf(w1.y, ei, E[5]); A[5] = fmaf(w1.y, ai, A[5]);
        E[6] = fmaf(w1.z, ei, E[6]); A[6] = fmaf(w1.z, ai, A[6]);
        E[7] = fmaf(w1.w, ei, E[7]); A[7] = fmaf(w1.w, ai, A[7]);
    }

    float nv[8], p2[8];
    #pragma unroll
    for (int k = 0; k < 8; k++) {
        float m = mrow[(sg * 8 + k) * 128 + d];
        nv[k] = m * (1.f - E[k]) + A[k];
        p2[k] = nv[k] * nv[k];
    }
    #pragma unroll
    for (int o = 16; o > 0; o >>= 1) {
        #pragma unroll
        for (int k = 0; k < 8; k++) p2[k] += __shfl_xor_sync(FULLM, p2[k], o);
    }
    const int wp = t >> 5, lane = t & 31;
    if (lane == 0) {
        #pragma unroll
        for (int k = 0; k < 8; k++) part[wp][k] = p2[k];
    }
    __syncthreads();
    if (t < 16) {
        float n2 = part[(t >> 3) * 4 + 0][t & 7] + part[(t >> 3) * 4 + 1][t & 7]
                 + part[(t >> 3) * 4 + 2][t & 7] + part[(t >> 3) * 4 + 3][t & 7];
        nsh[t] = fmaxf(sqrtf(n2), EPSN);
    }
    __syncthreads();
    #pragma unroll
    for (int k = 0; k < 8; k++)
        orow[(sg * 8 + k) * 128 + d] = nv[k] / nsh[sg * 8 + k];
}

// ---------------- launch: round-9 fork-join schedule (verified) -------------
//   main: mnorm -> gemmA (e1) -> attn (e3) -> scan -> scatter -> [wait e2] agent -> [wait e4]
//   s2:   [wait e1] gemmB (e2)
//   s3:   [wait e3] fuse (e4)
extern "C" void kernel_launch(void* const* d_in, const int* in_sizes, int n_in,
                              void* d_out, int out_size)
{
    const float* queries  = (const float*)d_in[0];
    const float* wqueries = (const float*)d_in[1];
    const float* memory   = (const float*)d_in[2];
    const float* Wq  = (const float*)d_in[3];
    const float* bq  = (const float*)d_in[4];
    const float* We  = (const float*)d_in[5];
    const float* be  = (const float*)d_in[6];
    const float* Wa  = (const float*)d_in[7];
    const float* ba  = (const float*)d_in[8];
    const float* Wf  = (const float*)d_in[9];
    const float* bf  = (const float*)d_in[10];
    const float* lng = (const float*)d_in[11];
    const float* lnb = (const float*)d_in[12];
    const float* Wg  = (const float*)d_in[13];
    const float* bg  = (const float*)d_in[14];
    const int*   idx = (const int*)d_in[15];

    float* outf = (float*)d_out;                 // fused_read [B,128]
    float* outm = outf + (size_t)BN * DD;        // new_memory [4096,16,128]

    const int gemm_smem = 2 * 128 * LDH * 2;     // 69632 bytes

    static cudaStream_t s2 = nullptr, s3 = nullptr;
    static cudaEvent_t e1, e2, e3, e4;
    if (s2 == nullptr) {
        cudaStreamCreateWithFlags(&s2, cudaStreamNonBlocking);
        cudaStreamCreateWithFlags(&s3, cudaStreamNonBlocking);
        cudaEventCreateWithFlags(&e1, cudaEventDisableTiming);
        cudaEventCreateWithFlags(&e2, cudaEventDisableTiming);
        cudaEventCreateWithFlags(&e3, cudaEventDisableTiming);
        cudaEventCreateWithFlags(&e4, cudaEventDisableTiming);
        cudaFuncSetAttribute(k_gemm_h, cudaFuncAttributeMaxDynamicSharedMemorySize, gemm_smem);
        cudaFuncSetAttribute(k_fuse_h, cudaFuncAttributeMaxDynamicSharedMemorySize, gemm_smem);
    }

    k_mnorm<<<NA * NS / 8, 256>>>(memory);                         // + zero counts
    k_gemm_h<<<dim3(BN / 128, 2), 256, gemm_smem>>>(
        queries, wqueries, Wq, bq, We, be, Wa, ba, 0);             // pqr, pqw
    cudaEventRecord(e1, (cudaStream_t)0);

    cudaStreamWaitEvent(s2, e1, 0);
    k_gemm_h<<<dim3(BN / 128, 2), 256, gemm_smem, s2>>>(
        queries, wqueries, Wq, bq, We, be, Wa, ba, 2);             // el, al
    cudaEventRecord(e2, s2);

    k_attn<<<BN / 8, 256>>>(memory, idx, wqueries, Wg, bg);
    cudaEventRecord(e3, (cudaStream_t)0);

    cudaStreamWaitEvent(s3, e3, 0);
    k_fuse_h<<<BN / 128, 256, gemm_smem, s3>>>(Wf, bf, lng, lnb, outf);
    cudaEventRecord(e4, s3);

    k_scan<<<1, 1024>>>();
    k_scatter<<<BN / 256, 256>>>(idx);
    cudaStreamWaitEvent((cudaStream_t)0, e2, 0);                   // join gemmB
    k_agent<<<NA, 256>>>(memory, outm);
    cudaStreamWaitEvent((cudaStream_t)0, e4, 0);                   // join fuse
}

// round 13
// speedup vs baseline: 1.1707x; 1.0089x over previous
#include <cuda_runtime.h>
#include <cuda_fp16.h>
#include <math.h>
#include <stdint.h>

#define BN 65536      // batch
#define DD 128        // dim
#define NS 16         // slots
#define NA 4096       // agents
#define EPSN 1e-12f
#define SCALEF 0.08838834764831845f   // 1/sqrt(128)
#define FULLM 0xffffffffu

// ---------------- scratch (fp16 intermediates; fp32 where precision-critical)
__device__ __half g_pqr[BN*DD];   // queries @ Wq^T + bq          (attn only)
__device__ __half g_pqw[BN*DD];   // write_queries @ Wq^T + bq    (attn only)
__device__ __half g_el[BN*DD];    // pre-sigmoid erase logits     (agent only)
__device__ __half g_al[BN*DD];    // pre-tanh add logits          (agent only)
__device__ __half g_read[BN*DD];  // attention read vectors       (fuse only)
__device__ float g_inten[BN];     // sigmoid(wq @ Wg^T + bg)
__device__ float g_ww[BN*NS];     // write softmax weights
__device__ float g_rmn[NA*NS];    // SCALEF / max(||mem[a,s]||, eps)
__device__ int   g_counts[NA];
__device__ int   g_offsets[NA];
__device__ int   g_cursor[NA];
__device__ int   g_bucket[BN];

// ---------------- per-(agent,slot) reciprocal norms + zero counts ----------
__global__ void k_mnorm(const float* __restrict__ mem) {
    int gt = blockIdx.x * blockDim.x + threadIdx.x;
    if (gt < NA) { g_counts[gt] = 0; g_cursor[gt] = 0; }
    int w = gt >> 5;   // 0..65535 slot rows
    int lane = threadIdx.x & 31;
    float4 v = *(const float4*)(mem + (size_t)w * 128 + lane * 4);
    float s = v.x*v.x + v.y*v.y + v.z*v.z + v.w*v.w;
    #pragma unroll
    for (int o = 16; o > 0; o >>= 1) s += __shfl_xor_sync(FULLM, s, o);
    if (lane == 0) g_rmn[w] = SCALEF / fmaxf(sqrtf(s), EPSN);
}

// ======================= fp16 tensor-core GEMM machinery ====================
#define LDH 136   // halves per row: 128 + 8 pad (272B rows)

__device__ __forceinline__ void ldsm4(uint32_t* r, uint32_t addr) {
    asm volatile("ldmatrix.sync.aligned.m8n8.x4.shared.b16 {%0,%1,%2,%3}, [%4];"
                 : "=r"(r[0]), "=r"(r[1]), "=r"(r[2]), "=r"(r[3]) : "r"(addr));
}
__device__ __forceinline__ void mma16816(float* c, const uint32_t* a, const uint32_t* b) {
    asm volatile("mma.sync.aligned.m16n8k16.row.col.f32.f16.f16.f32 "
                 "{%0,%1,%2,%3}, {%4,%5,%6,%7}, {%8,%9}, {%0,%1,%2,%3};"
                 : "+f"(c[0]), "+f"(c[1]), "+f"(c[2]), "+f"(c[3])
                 : "r"(a[0]), "r"(a[1]), "r"(a[2]), "r"(a[3]), "r"(b[0]), "r"(b[1]));
}
__device__ __forceinline__ uint2 f4_to_h4(float4 v) {
    __half2 h0 = __floats2half2_rn(v.x, v.y);
    __half2 h1 = __floats2half2_rn(v.z, v.w);
    uint2 u;
    u.x = *(uint32_t*)&h0;
    u.y = *(uint32_t*)&h1;
    return u;
}
__device__ __forceinline__ float4 h4_to_f4(uint2 u) {
    float2 a = __half22float2(*(__half2*)&u.x);
    float2 b = __half22float2(*(__half2*)&u.y);
    return make_float4(a.x, a.y, b.x, b.y);
}

// ---------------- 2x2-way projection GEMM: C[B,128] = X @ W^T + b (fp16 out)
__global__ void __launch_bounds__(256, 2)
k_gemm_h(const float* __restrict__ queries,
         const float* __restrict__ wqueries,
         const float* __restrict__ Wq, const float* __restrict__ bq,
         const float* __restrict__ We, const float* __restrict__ be,
         const float* __restrict__ Wa, const float* __restrict__ ba,
         int ybase)
{
    extern __shared__ char smraw[];
    __half* Xs = (__half*)smraw;            // [128][LDH]
    __half* Ws = Xs + 128 * LDH;            // [128][LDH]

    const float *X, *W, *bias;
    __half* out;
    switch (blockIdx.y + ybase) {
        case 0:  X = queries;  W = Wq; bias = bq; out = g_pqr; break;
        case 1:  X = wqueries; W = Wq; bias = bq; out = g_pqw; break;
        case 2:  X = wqueries; W = We; bias = be; out = g_el;  break;
        default: X = wqueries; W = Wa; bias = ba; out = g_al;  break;
    }

    const int t = threadIdx.x;
    const int lane = t & 31, wid = t >> 5;
    const int wm = wid & 3;        // 4 warp-rows -> 32 M each
    const int wn = wid >> 2;       // 2 warp-cols -> 64 N each
    const int row0 = blockIdx.x * 128;

    #pragma unroll
    for (int i = t; i < 4096; i += 256) {          // 128 rows x 32 float4
        int m = i >> 5, k4 = (i & 31) << 2;
        *(uint2*)(Xs + m * LDH + k4) =
            f4_to_h4(*(const float4*)(X + (size_t)(row0 + m) * 128 + k4));
    }
    #pragma unroll
    for (int i = t; i < 4096; i += 256) {
        int n = i >> 5, k4 = (i & 31) << 2;
        *(uint2*)(Ws + n * LDH + k4) =
            f4_to_h4(*(const float4*)(W + (size_t)n * 128 + k4));
    }
    __syncthreads();

    float acc[2][8][4];
    #pragma unroll
    for (int i = 0; i < 2; i++)
        #pragma unroll
        for (int j = 0; j < 8; j++)
            #pragma unroll
            for (int k = 0; k < 4; k++) acc[i][j][k] = 0.f;

    const uint32_t xsBase = (uint32_t)__cvta_generic_to_shared(Xs);
    const uint32_t wsBase = (uint32_t)__cvta_generic_to_shared(Ws);
    const uint32_t aAddr = xsBase +
        (((wm * 32 + (lane & 15)) * LDH + ((lane >> 4) << 3)) << 1);
    const uint32_t bAddr = wsBase +
        (((wn * 64 + ((lane >> 4) << 3) + (lane & 7)) * LDH + (((lane >> 3) & 1) << 3)) << 1);

    #pragma unroll
    for (int ks = 0; ks < 128; ks += 16) {
        uint32_t a[2][4];
        ldsm4(a[0], aAddr + (ks << 1));
        ldsm4(a[1], aAddr + ((16 * LDH + ks) << 1));
        uint32_t b[4][4];
        #pragma unroll
        for (int p = 0; p < 4; p++)
            ldsm4(b[p], bAddr + ((p * 16 * LDH + ks) << 1));
        #pragma unroll
        for (int mi = 0; mi < 2; mi++)
            #pragma unroll
            for (int p = 0; p < 4; p++) {
                mma16816(acc[mi][p * 2 + 0], a[mi], &b[p][0]);
                mma16816(acc[mi][p * 2 + 1], a[mi], &b[p][2]);
            }
    }

    const int cbase = wn * 64 + (lane & 3) * 2;
    const int rbase = row0 + wm * 32 + (lane >> 2);
    #pragma unroll
    for (int nj = 0; nj < 8; nj++) {
        int col = cbase + nj * 8;
        float b0 = bias[col], b1 = bias[col + 1];
        #pragma unroll
        for (int mi = 0; mi < 2; mi++) {
            float* c = acc[mi][nj];
            int r = rbase + mi * 16;
            __half2 h0 = __floats2half2_rn(c[0] + b0, c[1] + b1);
            __half2 h1 = __floats2half2_rn(c[2] + b0, c[3] + b1);
            *(uint32_t*)(out + (size_t)r * 128 + col) = *(uint32_t*)&h0;
            *(uint32_t*)(out + (size_t)(r + 8) * 128 + col) = *(uint32_t*)&h1;
        }
    }
}

// ---------------- fuse GEMM: outf = LN(gelu(g_read @ Wf^T + bf))*g + b ------
__global__ void __launch_bounds__(256, 2)
k_fuse_h(const float* __restrict__ Wf, const float* __restrict__ bf,
         const float* __restrict__ lng, const float* __restrict__ lnb,
         float* __restrict__ outf)
{
    extern __shared__ char smraw[];
    __half* Xs = (__half*)smraw;
    __half* Ws = Xs + 128 * LDH;

    const int t = threadIdx.x;
    const int lane = t & 31, wid = t >> 5;
    const int wm = wid & 3;
    const int wn = wid >> 2;
    const int row0 = blockIdx.x * 128;

    // X already fp16: straight uint4 copies (no conversion)
    #pragma unroll
    for (int i = t; i < 2048; i += 256) {          // 128 rows x 16 uint4
        int m = i >> 4, k8 = (i & 15) << 3;
        *(uint4*)(Xs + m * LDH + k8) =
            *(const uint4*)(g_read + (size_t)(row0 + m) * 128 + k8);
    }
    #pragma unroll
    for (int i = t; i < 4096; i += 256) {
        int n = i >> 5, k4 = (i & 31) << 2;
        *(uint2*)(Ws + n * LDH + k4) =
            f4_to_h4(*(const float4*)(Wf + (size_t)n * 128 + k4));
    }
    __syncthreads();

    float acc[2][8][4];
    #pragma unroll
    for (int i = 0; i < 2; i++)
        #pragma unroll
        for (int j = 0; j < 8; j++)
            #pragma unroll
            for (int k = 0; k < 4; k++) acc[i][j][k] = 0.f;

    const uint32_t xsBase = (uint32_t)__cvta_generic_to_shared(Xs);
    const uint32_t wsBase = (uint32_t)__cvta_generic_to_shared(Ws);
    const uint32_t aAddr = xsBase +
        (((wm * 32 + (lane & 15)) * LDH + ((lane >> 4) << 3)) << 1);
    const uint32_t bAddr = wsBase +
        (((wn * 64 + ((lane >> 4) << 3) + (lane & 7)) * LDH + (((lane >> 3) & 1) << 3)) << 1);

    #pragma unroll
    for (int ks = 0; ks < 128; ks += 16) {
        uint32_t a[2][4];
        ldsm4(a[0], aAddr + (ks << 1));
        ldsm4(a[1], aAddr + ((16 * LDH + ks) << 1));
        uint32_t b[4][4];
        #pragma unroll
        for (int p = 0; p < 4; p++)
            ldsm4(b[p], bAddr + ((p * 16 * LDH + ks) << 1));
        #pragma unroll
        for (int mi = 0; mi < 2; mi++)
            #pragma unroll
            for (int p = 0; p < 4; p++) {
                mma16816(acc[mi][p * 2 + 0], a[mi], &b[p][0]);
                mma16816(acc[mi][p * 2 + 1], a[mi], &b[p][2]);
            }
    }
    __syncthreads();   // before reusing smem for LN partials

    const float iSQ2 = 0.7071067811865476f;
    const int cbase = wn * 64 + (lane & 3) * 2;
    float sum[4] = {0.f, 0.f, 0.f, 0.f};
    float sq[4]  = {0.f, 0.f, 0.f, 0.f};

    #pragma unroll
    for (int nj = 0; nj < 8; nj++) {
        int col = cbase + nj * 8;
        float b0 = bf[col], b1 = bf[col + 1];
        #pragma unroll
        for (int mi = 0; mi < 2; mi++) {
            float* c = acc[mi][nj];
            #pragma unroll
            for (int q = 0; q < 4; q++) {
                float v = c[q] + ((q & 1) ? b1 : b0);
                v = 0.5f * v * (1.f + erff(v * iSQ2));
                c[q] = v;
                int ridx = mi * 2 + (q >> 1);
                sum[ridx] += v;
                sq[ridx] = fmaf(v, v, sq[ridx]);
            }
        }
    }
    #pragma unroll
    for (int o = 1; o <= 2; o <<= 1)
        #pragma unroll
        for (int ridx = 0; ridx < 4; ridx++) {
            sum[ridx] += __shfl_xor_sync(FULLM, sum[ridx], o);
            sq[ridx]  += __shfl_xor_sync(FULLM, sq[ridx], o);
        }

    float2* sums = (float2*)smraw;    // [128 local rows][2 wn] {sum, sq}
    if ((lane & 3) == 0) {
        #pragma unroll
        for (int ridx = 0; ridx < 4; ridx++) {
            int lr = wm * 32 + (lane >> 2) + (ridx >> 1) * 16 + (ridx & 1) * 8;
            sums[lr * 2 + wn] = make_float2(sum[ridx], sq[ridx]);
        }
    }
    __syncthreads();

    #pragma unroll
    for (int mi = 0; mi < 2; mi++) {
        #pragma unroll
        for (int h = 0; h < 2; h++) {
            int lr = wm * 32 + (lane >> 2) + mi * 16 + h * 8;
            float2 p0 = sums[lr * 2 + 0];
            float2 p1 = sums[lr * 2 + 1];
            float mu = (p0.x + p1.x) * (1.f / 128.f);
            float var = (p0.y + p1.y) * (1.f / 128.f) - mu * mu;
            float rstd = rsqrtf(var + 1e-5f);
            int r = row0 + lr;
            #pragma unroll
            for (int nj = 0; nj < 8; nj++) {
                int col = cbase + nj * 8;
                float v0 = (acc[mi][nj][h * 2 + 0] - mu) * rstd * lng[col] + lnb[col];
                float v1 = (acc[mi][nj][h * 2 + 1] - mu) * rstd * lng[col + 1] + lnb[col + 1];
                *(float2*)(outf + (size_t)r * 128 + col) = make_float2(v0, v1);
            }
        }
    }
}

// ---------------- exclusive scan of counts (4096), 1 block -----------------
__global__ void k_scan() {
    __shared__ int wsum[32];
    const int t = threadIdx.x;
    int v[4];
    #pragma unroll
    for (int i = 0; i < 4; i++) v[i] = g_counts[t * 4 + i];
    int sum = v[0] + v[1] + v[2] + v[3];
    const int lane = t & 31, w = t >> 5;
    int sc = sum;
    #pragma unroll
    for (int o = 1; o < 32; o <<= 1) {
        int n = __shfl_up_sync(FULLM, sc, o);
        if (lane >= o) sc += n;
    }
    if (lane == 31) wsum[w] = sc;
    __syncthreads();
    if (w == 0) {
        int ws = wsum[lane];
        #pragma unroll
        for (int o = 1; o < 32; o <<= 1) {
            int n = __shfl_up_sync(FULLM, ws, o);
            if (lane >= o) ws += n;
        }
        wsum[lane] = ws;
    }
    __syncthreads();
    int base = (w > 0 ? wsum[w - 1] : 0) + sc - sum;
    #pragma unroll
    for (int i = 0; i < 4; i++) { g_offsets[t * 4 + i] = base; base += v[i]; }
}

// ---------------- bucket scatter --------------------------------------------
__global__ void k_scatter(const int* __restrict__ idx) {
    int r = blockIdx.x * blockDim.x + threadIdx.x;
    if (r < BN) {
        int a = idx[r];
        int p = atomicAdd(&g_cursor[a], 1);
        g_bucket[g_offsets[a] + p] = r;
    }
}

// ---------------- paired warp reduction (for query norms) -------------------
__device__ __forceinline__ float pairred(float a0, float a1, int lane) {
    float x = (lane < 16) ? a1 : a0;
    x = __shfl_xor_sync(FULLM, x, 16);
    float t = ((lane < 16) ? a0 : a1) + x;
    t += __shfl_xor_sync(FULLM, t, 8);
    t += __shfl_xor_sync(FULLM, t, 4);
    t += __shfl_xor_sync(FULLM, t, 2);
    t += __shfl_xor_sync(FULLM, t, 1);
    return t;
}

// ---------------- fused attention (read+write) + intensity + histogram -----
__global__ void __launch_bounds__(256)
k_attn(const float* __restrict__ mem, const int* __restrict__ idx,
       const float* __restrict__ wq, const float* __restrict__ Wg,
       const float* __restrict__ bg)
{
    const int t = threadIdx.x, lane = t & 31;
    const int r = blockIdx.x * 8 + (t >> 5);
    const int a = idx[r];

    float4 qr = h4_to_f4(*(const uint2*)(g_pqr + (size_t)r * 128 + lane * 4));
    float4 qw = h4_to_f4(*(const uint2*)(g_pqw + (size_t)r * 128 + lane * 4));
    float nr0 = qr.x*qr.x + qr.y*qr.y + qr.z*qr.z + qr.w*qr.w;
    float nw0 = qw.x*qw.x + qw.y*qw.y + qw.z*qw.z + qw.w*qw.w;
    float nn = pairred(nr0, nw0, lane);        // lanes<16: |qr|^2, >=16: |qw|^2
    float inv = 1.f / fmaxf(sqrtf(nn), EPSN);

    // intensity: sigmoid(wq . Wg + bg) + agent histogram
    {
        float4 x = *(const float4*)(wq + (size_t)r * 128 + lane * 4);
        float4 g = *(const float4*)(Wg + lane * 4);
        float p = x.x * g.x + x.y * g.y + x.z * g.z + x.w * g.w;
        #pragma unroll
        for (int o = 16; o > 0; o >>= 1) p += __shfl_xor_sync(FULLM, p, o);
        if (lane == 0) {
            g_inten[r] = 1.f / (1.f + __expf(-(p + bg[0])));
            atomicAdd(&g_counts[a], 1);
        }
    }

    float rmn = g_rmn[a * 16 + (lane & 15)];   // reciprocal slot norms (pre-scaled)

    float ax = 0.f, ay = 0.f, az = 0.f, aw2 = 0.f, lr = 0.f, lw = 0.f, myw = 0.f;
    const float* mrow = mem + (size_t)a * 2048;
    #pragma unroll
    for (int j = 0; j < 8; j++) {
        const int s0 = 2 * j, s1 = 2 * j + 1;
        float4 m0 = *(const float4*)(mrow + s0 * 128 + lane * 4);
        float4 m1 = *(const float4*)(mrow + s1 * 128 + lane * 4);
        float p0 = m0.x*qr.x + m0.y*qr.y + m0.z*qr.z + m0.w*qr.w;   // m0.qr
        float p1 = m0.x*qw.x + m0.y*qw.y + m0.z*qw.z + m0.w*qw.w;   // m0.qw
        float p2 = m1.x*qr.x + m1.y*qr.y + m1.z*qr.z + m1.w*qr.w;   // m1.qr
        float p3 = m1.x*qw.x + m1.y*qw.y + m1.z*qw.z + m1.w*qw.w;   // m1.qw

        float x1 = (lane & 16) ? p0 : p1;
        x1 = __shfl_xor_sync(FULLM, x1, 16);
        float A = ((lane & 16) ? p1 : p0) + x1;
        float x2 = (lane & 16) ? p2 : p3;
        x2 = __shfl_xor_sync(FULLM, x2, 16);
        float Bv = ((lane & 16) ? p3 : p2) + x2;
        float x3 = (lane & 8) ? A : Bv;
        x3 = __shfl_xor_sync(FULLM, x3, 8);
        float C = ((lane & 8) ? Bv : A) + x3;      // octets: p0|p2|p1|p3
        C += __shfl_xor_sync(FULLM, C, 4);
        C += __shfl_xor_sync(FULLM, C, 2);
        C += __shfl_xor_sync(FULLM, C, 1);

        float rmnj = __shfl_sync(FULLM, rmn, s0 + ((lane >> 3) & 1));
        float e = __expf(C * inv * rmnj);          // one exp per thread
        float er0 = __shfl_sync(FULLM, e, 0);
        float er1 = __shfl_sync(FULLM, e, 8);
        float ew0 = __shfl_sync(FULLM, e, 16);
        float ew1 = __shfl_sync(FULLM, e, 24);
        lr += er0 + er1;
        lw += ew0 + ew1;
        ax  = fmaf(er0, m0.x, fmaf(er1, m1.x, ax));
        ay  = fmaf(er0, m0.y, fmaf(er1, m1.y, ay));
        az  = fmaf(er0, m0.z, fmaf(er1, m1.z, az));
        aw2 = fmaf(er0, m0.w, fmaf(er1, m1.w, aw2));
        if (lane == s0) myw = ew0;
        if (lane == s1) myw = ew1;
    }
    float invl = 1.f / lr;
    __half2 h0 = __floats2half2_rn(ax * invl, ay * invl);
    __half2 h1 = __floats2half2_rn(az * invl, aw2 * invl);
    uint2 u;
    u.x = *(uint32_t*)&h0;
    u.y = *(uint32_t*)&h1;
    *(uint2*)(g_read + (size_t)r * 128 + lane * 4) = u;
    if (lane < 16) g_ww[r * 16 + lane] = myw / lw;
}

// ---------------- per-agent gather-reduce + memory update + l2norm ---------
__global__ void k_agent(const float* __restrict__ mem, float* __restrict__ outm)
{
    __shared__ float part[8][8];
    __shared__ float nsh[16];
    const int a = blockIdx.x;
    const int t = threadIdx.x;
    const int d = t & 127;
    const int sg = t >> 7;
    const float* mrow = mem + (size_t)a * 2048;
    float* orow = outm + (size_t)a * 2048;
    const int cnt = g_counts[a];
    if (cnt == 0) {
        #pragma unroll
        for (int k = 0; k < 8; k++)
            orow[(sg * 8 + k) * 128 + d] = mrow[(sg * 8 + k) * 128 + d];
        return;
    }
    const int base = g_offsets[a];
    float E[8], A[8];
    #pragma unroll
    for (int k = 0; k < 8; k++) { E[k] = 0.f; A[k] = 0.f; }

    for (int i = 0; i < cnt; i++) {
        int r = g_bucket[base + i];
        float eld = __half2float(g_el[(size_t)r * 128 + d]);
        float ald = __half2float(g_al[(size_t)r * 128 + d]);
        float itn = g_inten[r];
        float4 w0 = *(const float4*)(g_ww + r * 16 + sg * 8);
        float4 w1 = *(const float4*)(g_ww + r * 16 + sg * 8 + 4);
        float ei = itn / (1.f + __expf(-eld));
        float ai = itn * (1.f - 2.f / (__expf(2.f * ald) + 1.f));
        E[0] = fmaf(w0.x, ei, E[0]); A[0] = fmaf(w0.x, ai, A[0]);
        E[1] = fmaf(w0.y, ei, E[1]); A[1] = fmaf(w0.y, ai, A[1]);
        E[2] = fmaf(w0.z, ei, E[2]); A[2] = fmaf(w0.z, ai, A[2]);
        E[3] = fmaf(w0.w, ei, E[3]); A[3] = fmaf(w0.w, ai, A[3]);
        E[4] = fmaf(w1.x, ei, E[4]); A[4] = fmaf(w1.x, ai, A[4]);
        E[5] = fmaf(w1.y, ei, E[5]); A[5] = fmaf(w1.y, ai, A[5]);
        E[6] = fmaf(w1.z, ei, E[6]); A[6] = fmaf(w1.z, ai, A[6]);
        E[7] = fmaf(w1.w, ei, E[7]); A[7] = fmaf(w1.w, ai, A[7]);
    }

    float nv[8], p2[8];
    #pragma unroll
    for (int k = 0; k < 8; k++) {
        float m = mrow[(sg * 8 + k) * 128 + d];
        nv[k] = m * (1.f - E[k]) + A[k];
        p2[k] = nv[k] * nv[k];
    }
    #pragma unroll
    for (int o = 16; o > 0; o >>= 1) {
        #pragma unroll
        for (int k = 0; k < 8; k++) p2[k] += __shfl_xor_sync(FULLM, p2[k], o);
    }
    const int wp = t >> 5, lane = t & 31;
    if (lane == 0) {
        #pragma unroll
        for (int k = 0; k < 8; k++) part[wp][k] = p2[k];
    }
    __syncthreads();
    if (t < 16) {
        float n2 = part[(t >> 3) * 4 + 0][t & 7] + part[(t >> 3) * 4 + 1][t & 7]
                 + part[(t >> 3) * 4 + 2][t & 7] + part[(t >> 3) * 4 + 3][t & 7];
        nsh[t] = fmaxf(sqrtf(n2), EPSN);
    }
    __syncthreads();
    #pragma unroll
    for (int k = 0; k < 8; k++)
        orow[(sg * 8 + k) * 128 + d] = nv[k] / nsh[sg * 8 + k];
}

// ---------------- launch: round-9 fork-join schedule (verified) -------------
extern "C" void kernel_launch(void* const* d_in, const int* in_sizes, int n_in,
                              void* d_out, int out_size)
{
    const float* queries  = (const float*)d_in[0];
    const float* wqueries = (const float*)d_in[1];
    const float* memory   = (const float*)d_in[2];
    const float* Wq  = (const float*)d_in[3];
    const float* bq  = (const float*)d_in[4];
    const float* We  = (const float*)d_in[5];
    const float* be  = (const float*)d_in[6];
    const float* Wa  = (const float*)d_in[7];
    const float* ba  = (const float*)d_in[8];
    const float* Wf  = (const float*)d_in[9];
    const float* bf  = (const float*)d_in[10];
    const float* lng = (const float*)d_in[11];
    const float* lnb = (const float*)d_in[12];
    const float* Wg  = (const float*)d_in[13];
    const float* bg  = (const float*)d_in[14];
    const int*   idx = (const int*)d_in[15];

    float* outf = (float*)d_out;                 // fused_read [B,128]
    float* outm = outf + (size_t)BN * DD;        // new_memory [4096,16,128]

    const int gemm_smem = 2 * 128 * LDH * 2;     // 69632 bytes

    static cudaStream_t s2 = nullptr, s3 = nullptr;
    static cudaEvent_t e1, e2, e3, e4;
    if (s2 == nullptr) {
        cudaStreamCreateWithFlags(&s2, cudaStreamNonBlocking);
        cudaStreamCreateWithFlags(&s3, cudaStreamNonBlocking);
        cudaEventCreateWithFlags(&e1, cudaEventDisableTiming);
        cudaEventCreateWithFlags(&e2, cudaEventDisableTiming);
        cudaEventCreateWithFlags(&e3, cudaEventDisableTiming);
        cudaEventCreateWithFlags(&e4, cudaEventDisableTiming);
        cudaFuncSetAttribute(k_gemm_h, cudaFuncAttributeMaxDynamicSharedMemorySize, gemm_smem);
        cudaFuncSetAttribute(k_fuse_h, cudaFuncAttributeMaxDynamicSharedMemorySize, gemm_smem);
    }

    k_mnorm<<<NA * NS / 8, 256>>>(memory);                         // + zero counts
    k_gemm_h<<<dim3(BN / 128, 2), 256, gemm_smem>>>(
        queries, wqueries, Wq, bq, We, be, Wa, ba, 0);             // pqr, pqw
    cudaEventRecord(e1, (cudaStream_t)0);

    cudaStreamWaitEvent(s2, e1, 0);
    k_gemm_h<<<dim3(BN / 128, 2), 256, gemm_smem, s2>>>(
        queries, wqueries, Wq, bq, We, be, Wa, ba, 2);             // el, al
    cudaEventRecord(e2, s2);

    k_attn<<<BN / 8, 256>>>(memory, idx, wqueries, Wg, bg);
    cudaEventRecord(e3, (cudaStream_t)0);

    cudaStreamWaitEvent(s3, e3, 0);
    k_fuse_h<<<BN / 128, 256, gemm_smem, s3>>>(Wf, bf, lng, lnb, outf);
    cudaEventRecord(e4, s3);

    k_scan<<<1, 1024>>>();
    k_scatter<<<BN / 256, 256>>>(idx);
    cudaStreamWaitEvent((cudaStream_t)0, e2, 0);                   // join gemmB
    k_agent<<<NA, 256>>>(memory, outm);
    cudaStreamWaitEvent((cudaStream_t)0, e4, 0);                   // join fuse
}

// round 14
// speedup vs baseline: 1.2460x; 1.0643x over previous
#include <cuda_runtime.h>
#include <cuda_fp16.h>
#include <math.h>
#include <stdint.h>

#define BN 65536      // batch
#define DD 128        // dim
#define NS 16         // slots
#define NA 4096       // agents
#define EPSN 1e-12f
#define SCALEF 0.08838834764831845f   // 1/sqrt(128)
#define FULLM 0xffffffffu

// ---------------- scratch (fp16 intermediates; fp32 where precision-critical)
__device__ __half g_pqr[BN*DD];   // queries @ Wq^T + bq          (attn only)
__device__ __half g_pqw[BN*DD];   // write_queries @ Wq^T + bq    (attn only)
__device__ __half g_el[BN*DD];    // pre-sigmoid erase logits     (agent only)
__device__ __half g_al[BN*DD];    // pre-tanh add logits          (agent only)
__device__ __half g_read[BN*DD];  // attention read vectors       (fuse only)
__device__ __half g_memh[NA*NS*DD]; // fp16 mirror of memory      (attn only)
__device__ float g_inten[BN];     // sigmoid(wq @ Wg^T + bg)
__device__ float g_ww[BN*NS];     // write softmax weights
__device__ float g_rmn[NA*NS];    // SCALEF / max(||mem[a,s]||, eps)
__device__ int   g_counts[NA];
__device__ int   g_offsets[NA];
__device__ int   g_cursor[NA];
__device__ int   g_bucket[BN];

__device__ __forceinline__ uint2 f4_to_h4(float4 v) {
    __half2 h0 = __floats2half2_rn(v.x, v.y);
    __half2 h1 = __floats2half2_rn(v.z, v.w);
    uint2 u;
    u.x = *(uint32_t*)&h0;
    u.y = *(uint32_t*)&h1;
    return u;
}
__device__ __forceinline__ float4 h4_to_f4(uint2 u) {
    float2 a = __half22float2(*(__half2*)&u.x);
    float2 b = __half22float2(*(__half2*)&u.y);
    return make_float4(a.x, a.y, b.x, b.y);
}

// ---------------- bookkeeping: zero + histogram ------------------------------
__global__ void k_zero() {
    int t = blockIdx.x * blockDim.x + threadIdx.x;
    if (t < NA) { g_counts[t] = 0; g_cursor[t] = 0; }
}
__global__ void k_hist(const int* __restrict__ idx) {
    int r = blockIdx.x * blockDim.x + threadIdx.x;
    if (r < BN) atomicAdd(&g_counts[idx[r]], 1);
}

// ---------------- per-(agent,slot) reciprocal norms + fp16 memory mirror ----
__global__ void k_mnorm(const float* __restrict__ mem) {
    int gt = blockIdx.x * blockDim.x + threadIdx.x;
    int w = gt >> 5;   // 0..65535 slot rows
    int lane = threadIdx.x & 31;
    float4 v = *(const float4*)(mem + (size_t)w * 128 + lane * 4);
    *(uint2*)(g_memh + (size_t)w * 128 + lane * 4) = f4_to_h4(v);
    float s = v.x*v.x + v.y*v.y + v.z*v.z + v.w*v.w;
    #pragma unroll
    for (int o = 16; o > 0; o >>= 1) s += __shfl_xor_sync(FULLM, s, o);
    if (lane == 0) g_rmn[w] = SCALEF / fmaxf(sqrtf(s), EPSN);
}

// ======================= fp16 tensor-core GEMM machinery ====================
#define LDH 136   // halves per row: 128 + 8 pad (272B rows)

__device__ __forceinline__ void ldsm4(uint32_t* r, uint32_t addr) {
    asm volatile("ldmatrix.sync.aligned.m8n8.x4.shared.b16 {%0,%1,%2,%3}, [%4];"
                 : "=r"(r[0]), "=r"(r[1]), "=r"(r[2]), "=r"(r[3]) : "r"(addr));
}
__device__ __forceinline__ void mma16816(float* c, const uint32_t* a, const uint32_t* b) {
    asm volatile("mma.sync.aligned.m16n8k16.row.col.f32.f16.f16.f32 "
                 "{%0,%1,%2,%3}, {%4,%5,%6,%7}, {%8,%9}, {%0,%1,%2,%3};"
                 : "+f"(c[0]), "+f"(c[1]), "+f"(c[2]), "+f"(c[3])
                 : "r"(a[0]), "r"(a[1]), "r"(a[2]), "r"(a[3]), "r"(b[0]), "r"(b[1]));
}

// ---------------- 2x2-way projection GEMM: C[B,128] = X @ W^T + b (fp16 out)
__global__ void __launch_bounds__(256, 2)
k_gemm_h(const float* __restrict__ queries,
         const float* __restrict__ wqueries,
         const float* __restrict__ Wq, const float* __restrict__ bq,
         const float* __restrict__ We, const float* __restrict__ be,
         const float* __restrict__ Wa, const float* __restrict__ ba,
         int ybase)
{
    extern __shared__ char smraw[];
    __half* Xs = (__half*)smraw;            // [128][LDH]
    __half* Ws = Xs + 128 * LDH;            // [128][LDH]

    const float *X, *W, *bias;
    __half* out;
    switch (blockIdx.y + ybase) {
        case 0:  X = queries;  W = Wq; bias = bq; out = g_pqr; break;
        case 1:  X = wqueries; W = Wq; bias = bq; out = g_pqw; break;
        case 2:  X = wqueries; W = We; bias = be; out = g_el;  break;
        default: X = wqueries; W = Wa; bias = ba; out = g_al;  break;
    }

    const int t = threadIdx.x;
    const int lane = t & 31, wid = t >> 5;
    const int wm = wid & 3;
    const int wn = wid >> 2;
    const int row0 = blockIdx.x * 128;

    #pragma unroll
    for (int i = t; i < 4096; i += 256) {
        int m = i >> 5, k4 = (i & 31) << 2;
        *(uint2*)(Xs + m * LDH + k4) =
            f4_to_h4(*(const float4*)(X + (size_t)(row0 + m) * 128 + k4));
    }
    #pragma unroll
    for (int i = t; i < 4096; i += 256) {
        int n = i >> 5, k4 = (i & 31) << 2;
        *(uint2*)(Ws + n * LDH + k4) =
            f4_to_h4(*(const float4*)(W + (size_t)n * 128 + k4));
    }
    __syncthreads();

    float acc[2][8][4];
    #pragma unroll
    for (int i = 0; i < 2; i++)
        #pragma unroll
        for (int j = 0; j < 8; j++)
            #pragma unroll
            for (int k = 0; k < 4; k++) acc[i][j][k] = 0.f;

    const uint32_t xsBase = (uint32_t)__cvta_generic_to_shared(Xs);
    const uint32_t wsBase = (uint32_t)__cvta_generic_to_shared(Ws);
    const uint32_t aAddr = xsBase +
        (((wm * 32 + (lane & 15)) * LDH + ((lane >> 4) << 3)) << 1);
    const uint32_t bAddr = wsBase +
        (((wn * 64 + ((lane >> 4) << 3) + (lane & 7)) * LDH + (((lane >> 3) & 1) << 3)) << 1);

    #pragma unroll
    for (int ks = 0; ks < 128; ks += 16) {
        uint32_t a[2][4];
        ldsm4(a[0], aAddr + (ks << 1));
        ldsm4(a[1], aAddr + ((16 * LDH + ks) << 1));
        uint32_t b[4][4];
        #pragma unroll
        for (int p = 0; p < 4; p++)
            ldsm4(b[p], bAddr + ((p * 16 * LDH + ks) << 1));
        #pragma unroll
        for (int mi = 0; mi < 2; mi++)
            #pragma unroll
            for (int p = 0; p < 4; p++) {
                mma16816(acc[mi][p * 2 + 0], a[mi], &b[p][0]);
                mma16816(acc[mi][p * 2 + 1], a[mi], &b[p][2]);
            }
    }

    const int cbase = wn * 64 + (lane & 3) * 2;
    const int rbase = row0 + wm * 32 + (lane >> 2);
    #pragma unroll
    for (int nj = 0; nj < 8; nj++) {
        int col = cbase + nj * 8;
        float b0 = bias[col], b1 = bias[col + 1];
        #pragma unroll
        for (int mi = 0; mi < 2; mi++) {
            float* c = acc[mi][nj];
            int r = rbase + mi * 16;
            __half2 h0 = __floats2half2_rn(c[0] + b0, c[1] + b1);
            __half2 h1 = __floats2half2_rn(c[2] + b0, c[3] + b1);
            *(uint32_t*)(out + (size_t)r * 128 + col) = *(uint32_t*)&h0;
            *(uint32_t*)(out + (size_t)(r + 8) * 128 + col) = *(uint32_t*)&h1;
        }
    }
}

// ---------------- fuse GEMM: outf = LN(gelu(g_read @ Wf^T + bf))*g + b ------
__global__ void __launch_bounds__(256, 2)
k_fuse_h(const float* __restrict__ Wf, const float* __restrict__ bf,
         const float* __restrict__ lng, const float* __restrict__ lnb,
         float* __restrict__ outf)
{
    extern __shared__ char smraw[];
    __half* Xs = (__half*)smraw;
    __half* Ws = Xs + 128 * LDH;

    const int t = threadIdx.x;
    const int lane = t & 31, wid = t >> 5;
    const int wm = wid & 3;
    const int wn = wid >> 2;
    const int row0 = blockIdx.x * 128;

    #pragma unroll
    for (int i = t; i < 2048; i += 256) {          // X already fp16
        int m = i >> 4, k8 = (i & 15) << 3;
        *(uint4*)(Xs + m * LDH + k8) =
            *(const uint4*)(g_read + (size_t)(row0 + m) * 128 + k8);
    }
    #pragma unroll
    for (int i = t; i < 4096; i += 256) {
        int n = i >> 5, k4 = (i & 31) << 2;
        *(uint2*)(Ws + n * LDH + k4) =
            f4_to_h4(*(const float4*)(Wf + (size_t)n * 128 + k4));
    }
    __syncthreads();

    float acc[2][8][4];
    #pragma unroll
    for (int i = 0; i < 2; i++)
        #pragma unroll
        for (int j = 0; j < 8; j++)
            #pragma unroll
            for (int k = 0; k < 4; k++) acc[i][j][k] = 0.f;

    const uint32_t xsBase = (uint32_t)__cvta_generic_to_shared(Xs);
    const uint32_t wsBase = (uint32_t)__cvta_generic_to_shared(Ws);
    const uint32_t aAddr = xsBase +
        (((wm * 32 + (lane & 15)) * LDH + ((lane >> 4) << 3)) << 1);
    const uint32_t bAddr = wsBase +
        (((wn * 64 + ((lane >> 4) << 3) + (lane & 7)) * LDH + (((lane >> 3) & 1) << 3)) << 1);

    #pragma unroll
    for (int ks = 0; ks < 128; ks += 16) {
        uint32_t a[2][4];
        ldsm4(a[0], aAddr + (ks << 1));
        ldsm4(a[1], aAddr + ((16 * LDH + ks) << 1));
        uint32_t b[4][4];
        #pragma unroll
        for (int p = 0; p < 4; p++)
            ldsm4(b[p], bAddr + ((p * 16 * LDH + ks) << 1));
        #pragma unroll
        for (int mi = 0; mi < 2; mi++)
            #pragma unroll
            for (int p = 0; p < 4; p++) {
                mma16816(acc[mi][p * 2 + 0], a[mi], &b[p][0]);
                mma16816(acc[mi][p * 2 + 1], a[mi], &b[p][2]);
            }
    }
    __syncthreads();

    const float iSQ2 = 0.7071067811865476f;
    const int cbase = wn * 64 + (lane & 3) * 2;
    float sum[4] = {0.f, 0.f, 0.f, 0.f};
    float sq[4]  = {0.f, 0.f, 0.f, 0.f};

    #pragma unroll
    for (int nj = 0; nj < 8; nj++) {
        int col = cbase + nj * 8;
        float b0 = bf[col], b1 = bf[col + 1];
        #pragma unroll
        for (int mi = 0; mi < 2; mi++) {
            float* c = acc[mi][nj];
            #pragma unroll
            for (int q = 0; q < 4; q++) {
                float v = c[q] + ((q & 1) ? b1 : b0);
                v = 0.5f * v * (1.f + erff(v * iSQ2));
                c[q] = v;
                int ridx = mi * 2 + (q >> 1);
                sum[ridx] += v;
                sq[ridx] = fmaf(v, v, sq[ridx]);
            }
        }
    }
    #pragma unroll
    for (int o = 1; o <= 2; o <<= 1)
        #pragma unroll
        for (int ridx = 0; ridx < 4; ridx++) {
            sum[ridx] += __shfl_xor_sync(FULLM, sum[ridx], o);
            sq[ridx]  += __shfl_xor_sync(FULLM, sq[ridx], o);
        }

    float2* sums = (float2*)smraw;
    if ((lane & 3) == 0) {
        #pragma unroll
        for (int ridx = 0; ridx < 4; ridx++) {
            int lr = wm * 32 + (lane >> 2) + (ridx >> 1) * 16 + (ridx & 1) * 8;
            sums[lr * 2 + wn] = make_float2(sum[ridx], sq[ridx]);
        }
    }
    __syncthreads();

    #pragma unroll
    for (int mi = 0; mi < 2; mi++) {
        #pragma unroll
        for (int h = 0; h < 2; h++) {
            int lr = wm * 32 + (lane >> 2) + mi * 16 + h * 8;
            float2 p0 = sums[lr * 2 + 0];
            float2 p1 = sums[lr * 2 + 1];
            float mu = (p0.x + p1.x) * (1.f / 128.f);
            float var = (p0.y + p1.y) * (1.f / 128.f) - mu * mu;
            float rstd = rsqrtf(var + 1e-5f);
            int r = row0 + lr;
            #pragma unroll
            for (int nj = 0; nj < 8; nj++) {
                int col = cbase + nj * 8;
                float v0 = (acc[mi][nj][h * 2 + 0] - mu) * rstd * lng[col] + lnb[col];
                float v1 = (acc[mi][nj][h * 2 + 1] - mu) * rstd * lng[col + 1] + lnb[col + 1];
                *(float2*)(outf + (size_t)r * 128 + col) = make_float2(v0, v1);
            }
        }
    }
}

// ---------------- exclusive scan of counts (4096), 1 block -----------------
__global__ void k_scan() {
    __shared__ int wsum[32];
    const int t = threadIdx.x;
    int v[4];
    #pragma unroll
    for (int i = 0; i < 4; i++) v[i] = g_counts[t * 4 + i];
    int sum = v[0] + v[1] + v[2] + v[3];
    const int lane = t & 31, w = t >> 5;
    int sc = sum;
    #pragma unroll
    for (int o = 1; o < 32; o <<= 1) {
        int n = __shfl_up_sync(FULLM, sc, o);
        if (lane >= o) sc += n;
    }
    if (lane == 31) wsum[w] = sc;
    __syncthreads();
    if (w == 0) {
        int ws = wsum[lane];
        #pragma unroll
        for (int o = 1; o < 32; o <<= 1) {
            int n = __shfl_up_sync(FULLM, ws, o);
            if (lane >= o) ws += n;
        }
        wsum[lane] = ws;
    }
    __syncthreads();
    int base = (w > 0 ? wsum[w - 1] : 0) + sc - sum;
    #pragma unroll
    for (int i = 0; i < 4; i++) { g_offsets[t * 4 + i] = base; base += v[i]; }
}

// ---------------- bucket scatter --------------------------------------------
__global__ void k_scatter(const int* __restrict__ idx) {
    int r = blockIdx.x * blockDim.x + threadIdx.x;
    if (r < BN) {
        int a = idx[r];
        int p = atomicAdd(&g_cursor[a], 1);
        g_bucket[g_offsets[a] + p] = r;
    }
}

// ---------------- paired warp reduction (for query norms) -------------------
__device__ __forceinline__ float pairred(float a0, float a1, int lane) {
    float x = (lane < 16) ? a1 : a0;
    x = __shfl_xor_sync(FULLM, x, 16);
    float t = ((lane < 16) ? a0 : a1) + x;
    t += __shfl_xor_sync(FULLM, t, 8);
    t += __shfl_xor_sync(FULLM, t, 4);
    t += __shfl_xor_sync(FULLM, t, 2);
    t += __shfl_xor_sync(FULLM, t, 1);
    return t;
}

// ---------------- fused attention (read+write) + intensity ------------------
__global__ void __launch_bounds__(256)
k_attn(const int* __restrict__ idx,
       const float* __restrict__ wq, const float* __restrict__ Wg,
       const float* __restrict__ bg)
{
    const int t = threadIdx.x, lane = t & 31;
    const int r = blockIdx.x * 8 + (t >> 5);
    const int a = idx[r];

    float4 qr = h4_to_f4(*(const uint2*)(g_pqr + (size_t)r * 128 + lane * 4));
    float4 qw = h4_to_f4(*(const uint2*)(g_pqw + (size_t)r * 128 + lane * 4));
    float nr0 = qr.x*qr.x + qr.y*qr.y + qr.z*qr.z + qr.w*qr.w;
    float nw0 = qw.x*qw.x + qw.y*qw.y + qw.z*qw.z + qw.w*qw.w;
    float nn = pairred(nr0, nw0, lane);        // lanes<16: |qr|^2, >=16: |qw|^2
    float inv = 1.f / fmaxf(sqrtf(nn), EPSN);

    // intensity: sigmoid(wq . Wg + bg)
    {
        float4 x = *(const float4*)(wq + (size_t)r * 128 + lane * 4);
        float4 g = *(const float4*)(Wg + lane * 4);
        float p = x.x * g.x + x.y * g.y + x.z * g.z + x.w * g.w;
        #pragma unroll
        for (int o = 16; o > 0; o >>= 1) p += __shfl_xor_sync(FULLM, p, o);
        if (lane == 0) g_inten[r] = 1.f / (1.f + __expf(-(p + bg[0])));
    }

    float rmn = g_rmn[a * 16 + (lane & 15)];   // reciprocal slot norms (pre-scaled)

    float ax = 0.f, ay = 0.f, az = 0.f, aw2 = 0.f, lr = 0.f, lw = 0.f, myw = 0.f;
    const __half* mrow = g_memh + (size_t)a * 2048;
    #pragma unroll
    for (int j = 0; j < 8; j++) {
        const int s0 = 2 * j, s1 = 2 * j + 1;
        float4 m0 = h4_to_f4(*(const uint2*)(mrow + s0 * 128 + lane * 4));
        float4 m1 = h4_to_f4(*(const uint2*)(mrow + s1 * 128 + lane * 4));
        float p0 = m0.x*qr.x + m0.y*qr.y + m0.z*qr.z + m0.w*qr.w;   // m0.qr
        float p1 = m0.x*qw.x + m0.y*qw.y + m0.z*qw.z + m0.w*qw.w;   // m0.qw
        float p2 = m1.x*qr.x + m1.y*qr.y + m1.z*qr.z + m1.w*qr.w;   // m1.qr
        float p3 = m1.x*qw.x + m1.y*qw.y + m1.z*qw.z + m1.w*qw.w;   // m1.qw

        float x1 = (lane & 16) ? p0 : p1;
        x1 = __shfl_xor_sync(FULLM, x1, 16);
        float A = ((lane & 16) ? p1 : p0) + x1;
        float x2 = (lane & 16) ? p2 : p3;
        x2 = __shfl_xor_sync(FULLM, x2, 16);
        float Bv = ((lane & 16) ? p3 : p2) + x2;
        float x3 = (lane & 8) ? A : Bv;
        x3 = __shfl_xor_sync(FULLM, x3, 8);
        float C = ((lane & 8) ? Bv : A) + x3;      // octets: p0|p2|p1|p3
        C += __shfl_xor_sync(FULLM, C, 4);
        C += __shfl_xor_sync(FULLM, C, 2);
        C += __shfl_xor_sync(FULLM, C, 1);

        float rmnj = __shfl_sync(FULLM, rmn, s0 + ((lane >> 3) & 1));
        float e = __expf(C * inv * rmnj);          // one exp per thread
        float er0 = __shfl_sync(FULLM, e, 0);
        float er1 = __shfl_sync(FULLM, e, 8);
        float ew0 = __shfl_sync(FULLM, e, 16);
        float ew1 = __shfl_sync(FULLM, e, 24);
        lr += er0 + er1;
        lw += ew0 + ew1;
        ax  = fmaf(er0, m0.x, fmaf(er1, m1.x, ax));
        ay  = fmaf(er0, m0.y, fmaf(er1, m1.y, ay));
        az  = fmaf(er0, m0.z, fmaf(er1, m1.z, az));
        aw2 = fmaf(er0, m0.w, fmaf(er1, m1.w, aw2));
        if (lane == s0) myw = ew0;
        if (lane == s1) myw = ew1;
    }
    float invl = 1.f / lr;
    __half2 h0 = __floats2half2_rn(ax * invl, ay * invl);
    __half2 h1 = __floats2half2_rn(az * invl, aw2 * invl);
    uint2 u;
    u.x = *(uint32_t*)&h0;
    u.y = *(uint32_t*)&h1;
    *(uint2*)(g_read + (size_t)r * 128 + lane * 4) = u;
    if (lane < 16) g_ww[r * 16 + lane] = myw / lw;
}

// ---------------- per-agent gather-reduce + memory update + l2norm ---------
__global__ void k_agent(const float* __restrict__ mem, float* __restrict__ outm)
{
    __shared__ float part[8][8];
    __shared__ float nsh[16];
    const int a = blockIdx.x;
    const int t = threadIdx.x;
    const int d = t & 127;
    const int sg = t >> 7;
    const float* mrow = mem + (size_t)a * 2048;
    float* orow = outm + (size_t)a * 2048;
    const int cnt = g_counts[a];
    if (cnt == 0) {
        #pragma unroll
        for (int k = 0; k < 8; k++)
            orow[(sg * 8 + k) * 128 + d] = mrow[(sg * 8 + k) * 128 + d];
        return;
    }
    const int base = g_offsets[a];
    float E[8], A[8];
    #pragma unroll
    for (int k = 0; k < 8; k++) { E[k] = 0.f; A[k] = 0.f; }

    for (int i = 0; i < cnt; i++) {
        int r = g_bucket[base + i];
        float eld = __half2float(g_el[(size_t)r * 128 + d]);
        float ald = __half2float(g_al[(size_t)r * 128 + d]);
        float itn = g_inten[r];
        float4 w0 = *(const float4*)(g_ww + r * 16 + sg * 8);
        float4 w1 = *(const float4*)(g_ww + r * 16 + sg * 8 + 4);
        float ei = itn / (1.f + __expf(-eld));
        float ai = itn * (1.f - 2.f / (__expf(2.f * ald) + 1.f));
        E[0] = fmaf(w0.x, ei, E[0]); A[0] = fmaf(w0.x, ai, A[0]);
        E[1] = fmaf(w0.y, ei, E[1]); A[1] = fmaf(w0.y, ai, A[1]);
        E[2] = fmaf(w0.z, ei, E[2]); A[2] = fmaf(w0.z, ai, A[2]);
        E[3] = fmaf(w0.w, ei, E[3]); A[3] = fmaf(w0.w, ai, A[3]);
        E[4] = fmaf(w1.x, ei, E[4]); A[4] = fmaf(w1.x, ai, A[4]);
        E[5] = fmaf(w1.y, ei, E[5]); A[5] = fmaf(w1.y, ai, A[5]);
        E[6] = fmaf(w1.z, ei, E[6]); A[6] = fmaf(w1.z, ai, A[6]);
        E[7] = fmaf(w1.w, ei, E[7]); A[7] = fmaf(w1.w, ai, A[7]);
    }

    float nv[8], p2[8];
    #pragma unroll
    for (int k = 0; k < 8; k++) {
        float m = mrow[(sg * 8 + k) * 128 + d];
        nv[k] = m * (1.f - E[k]) + A[k];
        p2[k] = nv[k] * nv[k];
    }
    #pragma unroll
    for (int o = 16; o > 0; o >>= 1) {
        #pragma unroll
        for (int k = 0; k < 8; k++) p2[k] += __shfl_xor_sync(FULLM, p2[k], o);
    }
    const int wp = t >> 5, lane = t & 31;
    if (lane == 0) {
        #pragma unroll
        for (int k = 0; k < 8; k++) part[wp][k] = p2[k];
    }
    __syncthreads();
    if (t < 16) {
        float n2 = part[(t >> 3) * 4 + 0][t & 7] + part[(t >> 3) * 4 + 1][t & 7]
                 + part[(t >> 3) * 4 + 2][t & 7] + part[(t >> 3) * 4 + 3][t & 7];
        nsh[t] = fmaxf(sqrtf(n2), EPSN);
    }
    __syncthreads();
    #pragma unroll
    for (int k = 0; k < 8; k++)
        orow[(sg * 8 + k) * 128 + d] = nv[k] / nsh[sg * 8 + k];
}

// ---------------- launch: fork-join graph ------------------------------------
//   main: (e0) mnorm -> gemmA (e1) -> attn (e3) -> [wait e2b] agent -> [wait e4]
//   s2:   [wait e0] zero -> hist -> scan -> scatter -> [wait e1] gemmB (e2b)
//   s3:   [wait e3] fuse (e4)
extern "C" void kernel_launch(void* const* d_in, const int* in_sizes, int n_in,
                              void* d_out, int out_size)
{
    const float* queries  = (const float*)d_in[0];
    const float* wqueries = (const float*)d_in[1];
    const float* memory   = (const float*)d_in[2];
    const float* Wq  = (const float*)d_in[3];
    const float* bq  = (const float*)d_in[4];
    const float* We  = (const float*)d_in[5];
    const float* be  = (const float*)d_in[6];
    const float* Wa  = (const float*)d_in[7];
    const float* ba  = (const float*)d_in[8];
    const float* Wf  = (const float*)d_in[9];
    const float* bf  = (const float*)d_in[10];
    const float* lng = (const float*)d_in[11];
    const float* lnb = (const float*)d_in[12];
    const float* Wg  = (const float*)d_in[13];
    const float* bg  = (const float*)d_in[14];
    const int*   idx = (const int*)d_in[15];

    float* outf = (float*)d_out;                 // fused_read [B,128]
    float* outm = outf + (size_t)BN * DD;        // new_memory [4096,16,128]

    const int gemm_smem = 2 * 128 * LDH * 2;     // 69632 bytes

    static cudaStream_t s2 = nullptr, s3 = nullptr;
    static cudaEvent_t e0, e1, e2b, e3, e4;
    if (s2 == nullptr) {
        cudaStreamCreateWithFlags(&s2, cudaStreamNonBlocking);
        cudaStreamCreateWithFlags(&s3, cudaStreamNonBlocking);
        cudaEventCreateWithFlags(&e0,  cudaEventDisableTiming);
        cudaEventCreateWithFlags(&e1,  cudaEventDisableTiming);
        cudaEventCreateWithFlags(&e2b, cudaEventDisableTiming);
        cudaEventCreateWithFlags(&e3,  cudaEventDisableTiming);
        cudaEventCreateWithFlags(&e4,  cudaEventDisableTiming);
        cudaFuncSetAttribute(k_gemm_h, cudaFuncAttributeMaxDynamicSharedMemorySize, gemm_smem);
        cudaFuncSetAttribute(k_fuse_h, cudaFuncAttributeMaxDynamicSharedMemorySize, gemm_smem);
    }

    // fork point (legal capture fork — round-10 lesson)
    cudaEventRecord(e0, (cudaStream_t)0);

    // side chain: bucket construction, overlaps mnorm+gemmA
    cudaStreamWaitEvent(s2, e0, 0);
    k_zero<<<16, 256, 0, s2>>>();
    k_hist<<<BN / 256, 256, 0, s2>>>(idx);
    k_scan<<<1, 1024, 0, s2>>>();
    k_scatter<<<BN / 256, 256, 0, s2>>>(idx);

    // main: fp16 memory mirror + slot norms, then attention projections
    k_mnorm<<<NA * NS / 8, 256>>>(memory);
    k_gemm_h<<<dim3(BN / 128, 2), 256, gemm_smem>>>(
        queries, wqueries, Wq, bq, We, be, Wa, ba, 0);             // pqr, pqw
    cudaEventRecord(e1, (cudaStream_t)0);

    // side: erase/add projections (needed only by k_agent)
    cudaStreamWaitEvent(s2, e1, 0);
    k_gemm_h<<<dim3(BN / 128, 2), 256, gemm_smem, s2>>>(
        queries, wqueries, Wq, bq, We, be, Wa, ba, 2);             // el, al
    cudaEventRecord(e2b, s2);

    // main: attention
    k_attn<<<BN / 8, 256>>>(idx, wqueries, Wg, bg);
    cudaEventRecord(e3, (cudaStream_t)0);

    // side: fuse (overlaps agent)
    cudaStreamWaitEvent(s3, e3, 0);
    k_fuse_h<<<BN / 128, 256, gemm_smem, s3>>>(Wf, bf, lng, lnb, outf);
    cudaEventRecord(e4, s3);

    // main: memory update (e2b covers bucket chain + gemmB, same stream)
    cudaStreamWaitEvent((cudaStream_t)0, e2b, 0);
    k_agent<<<NA, 256>>>(memory, outm);
    cudaStreamWaitEvent((cudaStream_t)0, e4, 0);
}

// round 15
// speedup vs baseline: 1.2667x; 1.0167x over previous
#include <cuda_runtime.h>
#include <cuda_fp16.h>
#include <math.h>
#include <stdint.h>

#define BN 65536      // batch
#define DD 128        // dim
#define NS 16         // slots
#define NA 4096       // agents
#define EPSN 1e-12f
#define SCALEF 0.08838834764831845f   // 1/sqrt(128)
#define FULLM 0xffffffffu

// ---------------- scratch (fp16 intermediates; fp32 where precision-critical)
__device__ __half g_pqr[BN*DD];   // queries @ Wq^T + bq          (attn only)
__device__ __half g_pqw[BN*DD];   // write_queries @ Wq^T + bq    (attn only)
__device__ __half g_el[BN*DD];    // pre-sigmoid erase logits     (agent only)
__device__ __half g_al[BN*DD];    // pre-tanh add logits          (agent only)
__device__ __half g_read[BN*DD];  // attention read vectors       (fuse only)
__device__ __half g_memh[NA*NS*DD]; // fp16 mirror of memory      (attn only)
__device__ float g_inten[BN];     // sigmoid(wq @ Wg^T + bg)
__device__ float g_ww[BN*NS];     // write softmax weights
__device__ float g_rmn[NA*NS];    // SCALEF / max(||mem[a,s]||, eps)
__device__ int   g_counts[NA];
__device__ int   g_offsets[NA];
__device__ int   g_cursor[NA];
__device__ int   g_bucket[BN];

__device__ __forceinline__ uint2 f4_to_h4(float4 v) {
    __half2 h0 = __floats2half2_rn(v.x, v.y);
    __half2 h1 = __floats2half2_rn(v.z, v.w);
    uint2 u;
    u.x = *(uint32_t*)&h0;
    u.y = *(uint32_t*)&h1;
    return u;
}
__device__ __forceinline__ float4 h4_to_f4(uint2 u) {
    float2 a = __half22float2(*(__half2*)&u.x);
    float2 b = __half22float2(*(__half2*)&u.y);
    return make_float4(a.x, a.y, b.x, b.y);
}
// pair-fold: lanes with (lane&m)==0 end on x-path, else y-path
__device__ __forceinline__ float ffold(float x, float y, int m, int lane) {
    float sel = (lane & m) ? x : y;
    float o = __shfl_xor_sync(FULLM, sel, m);
    return ((lane & m) ? y : x) + o;
}

// ---------------- bookkeeping: zero + histogram ------------------------------
__global__ void k_zero() {
    int t = blockIdx.x * blockDim.x + threadIdx.x;
    if (t < NA) { g_counts[t] = 0; g_cursor[t] = 0; }
}
__global__ void k_hist(const int* __restrict__ idx) {
    int r = blockIdx.x * blockDim.x + threadIdx.x;
    if (r < BN) atomicAdd(&g_counts[idx[r]], 1);
}

// ---------------- per-(agent,slot) reciprocal norms + fp16 memory mirror ----
__global__ void k_mnorm(const float* __restrict__ mem) {
    int gt = blockIdx.x * blockDim.x + threadIdx.x;
    int w = gt >> 5;   // 0..65535 slot rows
    int lane = threadIdx.x & 31;
    float4 v = *(const float4*)(mem + (size_t)w * 128 + lane * 4);
    *(uint2*)(g_memh + (size_t)w * 128 + lane * 4) = f4_to_h4(v);
    float s = v.x*v.x + v.y*v.y + v.z*v.z + v.w*v.w;
    #pragma unroll
    for (int o = 16; o > 0; o >>= 1) s += __shfl_xor_sync(FULLM, s, o);
    if (lane == 0) g_rmn[w] = SCALEF / fmaxf(sqrtf(s), EPSN);
}

// ======================= fp16 tensor-core GEMM machinery ====================
#define LDH 136   // halves per row: 128 + 8 pad (272B rows)

__device__ __forceinline__ void ldsm4(uint32_t* r, uint32_t addr) {
    asm volatile("ldmatrix.sync.aligned.m8n8.x4.shared.b16 {%0,%1,%2,%3}, [%4];"
                 : "=r"(r[0]), "=r"(r[1]), "=r"(r[2]), "=r"(r[3]) : "r"(addr));
}
__device__ __forceinline__ void mma16816(float* c, const uint32_t* a, const uint32_t* b) {
    asm volatile("mma.sync.aligned.m16n8k16.row.col.f32.f16.f16.f32 "
                 "{%0,%1,%2,%3}, {%4,%5,%6,%7}, {%8,%9}, {%0,%1,%2,%3};"
                 : "+f"(c[0]), "+f"(c[1]), "+f"(c[2]), "+f"(c[3])
                 : "r"(a[0]), "r"(a[1]), "r"(a[2]), "r"(a[3]), "r"(b[0]), "r"(b[1]));
}

// ---------------- 2x2-way projection GEMM: C[B,128] = X @ W^T + b (fp16 out)
__global__ void __launch_bounds__(256, 2)
k_gemm_h(const float* __restrict__ queries,
         const float* __restrict__ wqueries,
         const float* __restrict__ Wq, const float* __restrict__ bq,
         const float* __restrict__ We, const float* __restrict__ be,
         const float* __restrict__ Wa, const float* __restrict__ ba,
         int ybase)
{
    extern __shared__ char smraw[];
    __half* Xs = (__half*)smraw;            // [128][LDH]
    __half* Ws = Xs + 128 * LDH;            // [128][LDH]

    const float *X, *W, *bias;
    __half* out;
    switch (blockIdx.y + ybase) {
        case 0:  X = queries;  W = Wq; bias = bq; out = g_pqr; break;
        case 1:  X = wqueries; W = Wq; bias = bq; out = g_pqw; break;
        case 2:  X = wqueries; W = We; bias = be; out = g_el;  break;
        default: X = wqueries; W = Wa; bias = ba; out = g_al;  break;
    }

    const int t = threadIdx.x;
    const int lane = t & 31, wid = t >> 5;
    const int wm = wid & 3;
    const int wn = wid >> 2;
    const int row0 = blockIdx.x * 128;

    #pragma unroll
    for (int i = t; i < 4096; i += 256) {
        int m = i >> 5, k4 = (i & 31) << 2;
        *(uint2*)(Xs + m * LDH + k4) =
            f4_to_h4(*(const float4*)(X + (size_t)(row0 + m) * 128 + k4));
    }
    #pragma unroll
    for (int i = t; i < 4096; i += 256) {
        int n = i >> 5, k4 = (i & 31) << 2;
        *(uint2*)(Ws + n * LDH + k4) =
            f4_to_h4(*(const float4*)(W + (size_t)n * 128 + k4));
    }
    __syncthreads();

    float acc[2][8][4];
    #pragma unroll
    for (int i = 0; i < 2; i++)
        #pragma unroll
        for (int j = 0; j < 8; j++)
            #pragma unroll
            for (int k = 0; k < 4; k++) acc[i][j][k] = 0.f;

    const uint32_t xsBase = (uint32_t)__cvta_generic_to_shared(Xs);
    const uint32_t wsBase = (uint32_t)__cvta_generic_to_shared(Ws);
    const uint32_t aAddr = xsBase +
        (((wm * 32 + (lane & 15)) * LDH + ((lane >> 4) << 3)) << 1);
    const uint32_t bAddr = wsBase +
        (((wn * 64 + ((lane >> 4) << 3) + (lane & 7)) * LDH + (((lane >> 3) & 1) << 3)) << 1);

    #pragma unroll
    for (int ks = 0; ks < 128; ks += 16) {
        uint32_t a[2][4];
        ldsm4(a[0], aAddr + (ks << 1));
        ldsm4(a[1], aAddr + ((16 * LDH + ks) << 1));
        uint32_t b[4][4];
        #pragma unroll
        for (int p = 0; p < 4; p++)
            ldsm4(b[p], bAddr + ((p * 16 * LDH + ks) << 1));
        #pragma unroll
        for (int mi = 0; mi < 2; mi++)
            #pragma unroll
            for (int p = 0; p < 4; p++) {
                mma16816(acc[mi][p * 2 + 0], a[mi], &b[p][0]);
                mma16816(acc[mi][p * 2 + 1], a[mi], &b[p][2]);
            }
    }

    const int cbase = wn * 64 + (lane & 3) * 2;
    const int rbase = row0 + wm * 32 + (lane >> 2);
    #pragma unroll
    for (int nj = 0; nj < 8; nj++) {
        int col = cbase + nj * 8;
        float b0 = bias[col], b1 = bias[col + 1];
        #pragma unroll
        for (int mi = 0; mi < 2; mi++) {
            float* c = acc[mi][nj];
            int r = rbase + mi * 16;
            __half2 h0 = __floats2half2_rn(c[0] + b0, c[1] + b1);
            __half2 h1 = __floats2half2_rn(c[2] + b0, c[3] + b1);
            *(uint32_t*)(out + (size_t)r * 128 + col) = *(uint32_t*)&h0;
            *(uint32_t*)(out + (size_t)(r + 8) * 128 + col) = *(uint32_t*)&h1;
        }
    }
}

// ---------------- fuse GEMM: outf = LN(gelu(g_read @ Wf^T + bf))*g + b ------
__global__ void __launch_bounds__(256, 2)
k_fuse_h(const float* __restrict__ Wf, const float* __restrict__ bf,
         const float* __restrict__ lng, const float* __restrict__ lnb,
         float* __restrict__ outf)
{
    extern __shared__ char smraw[];
    __half* Xs = (__half*)smraw;
    __half* Ws = Xs + 128 * LDH;

    const int t = threadIdx.x;
    const int lane = t & 31, wid = t >> 5;
    const int wm = wid & 3;
    const int wn = wid >> 2;
    const int row0 = blockIdx.x * 128;

    #pragma unroll
    for (int i = t; i < 2048; i += 256) {          // X already fp16
        int m = i >> 4, k8 = (i & 15) << 3;
        *(uint4*)(Xs + m * LDH + k8) =
            *(const uint4*)(g_read + (size_t)(row0 + m) * 128 + k8);
    }
    #pragma unroll
    for (int i = t; i < 4096; i += 256) {
        int n = i >> 5, k4 = (i & 31) << 2;
        *(uint2*)(Ws + n * LDH + k4) =
            f4_to_h4(*(const float4*)(Wf + (size_t)n * 128 + k4));
    }
    __syncthreads();

    float acc[2][8][4];
    #pragma unroll
    for (int i = 0; i < 2; i++)
        #pragma unroll
        for (int j = 0; j < 8; j++)
            #pragma unroll
            for (int k = 0; k < 4; k++) acc[i][j][k] = 0.f;

    const uint32_t xsBase = (uint32_t)__cvta_generic_to_shared(Xs);
    const uint32_t wsBase = (uint32_t)__cvta_generic_to_shared(Ws);
    const uint32_t aAddr = xsBase +
        (((wm * 32 + (lane & 15)) * LDH + ((lane >> 4) << 3)) << 1);
    const uint32_t bAddr = wsBase +
        (((wn * 64 + ((lane >> 4) << 3) + (lane & 7)) * LDH + (((lane >> 3) & 1) << 3)) << 1);

    #pragma unroll
    for (int ks = 0; ks < 128; ks += 16) {
        uint32_t a[2][4];
        ldsm4(a[0], aAddr + (ks << 1));
        ldsm4(a[1], aAddr + ((16 * LDH + ks) << 1));
        uint32_t b[4][4];
        #pragma unroll
        for (int p = 0; p < 4; p++)
            ldsm4(b[p], bAddr + ((p * 16 * LDH + ks) << 1));
        #pragma unroll
        for (int mi = 0; mi < 2; mi++)
            #pragma unroll
            for (int p = 0; p < 4; p++) {
                mma16816(acc[mi][p * 2 + 0], a[mi], &b[p][0]);
                mma16816(acc[mi][p * 2 + 1], a[mi], &b[p][2]);
            }
    }
    __syncthreads();

    const float iSQ2 = 0.7071067811865476f;
    const int cbase = wn * 64 + (lane & 3) * 2;
    float sum[4] = {0.f, 0.f, 0.f, 0.f};
    float sq[4]  = {0.f, 0.f, 0.f, 0.f};

    #pragma unroll
    for (int nj = 0; nj < 8; nj++) {
        int col = cbase + nj * 8;
        float b0 = bf[col], b1 = bf[col + 1];
        #pragma unroll
        for (int mi = 0; mi < 2; mi++) {
            float* c = acc[mi][nj];
            #pragma unroll
            for (int q = 0; q < 4; q++) {
                float v = c[q] + ((q & 1) ? b1 : b0);
                v = 0.5f * v * (1.f + erff(v * iSQ2));
                c[q] = v;
                int ridx = mi * 2 + (q >> 1);
                sum[ridx] += v;
                sq[ridx] = fmaf(v, v, sq[ridx]);
            }
        }
    }
    #pragma unroll
    for (int o = 1; o <= 2; o <<= 1)
        #pragma unroll
        for (int ridx = 0; ridx < 4; ridx++) {
            sum[ridx] += __shfl_xor_sync(FULLM, sum[ridx], o);
            sq[ridx]  += __shfl_xor_sync(FULLM, sq[ridx], o);
        }

    float2* sums = (float2*)smraw;
    if ((lane & 3) == 0) {
        #pragma unroll
        for (int ridx = 0; ridx < 4; ridx++) {
            int lr = wm * 32 + (lane >> 2) + (ridx >> 1) * 16 + (ridx & 1) * 8;
            sums[lr * 2 + wn] = make_float2(sum[ridx], sq[ridx]);
        }
    }
    __syncthreads();

    #pragma unroll
    for (int mi = 0; mi < 2; mi++) {
        #pragma unroll
        for (int h = 0; h < 2; h++) {
            int lr = wm * 32 + (lane >> 2) + mi * 16 + h * 8;
            float2 p0 = sums[lr * 2 + 0];
            float2 p1 = sums[lr * 2 + 1];
            float mu = (p0.x + p1.x) * (1.f / 128.f);
            float var = (p0.y + p1.y) * (1.f / 128.f) - mu * mu;
            float rstd = rsqrtf(var + 1e-5f);
            int r = row0 + lr;
            #pragma unroll
            for (int nj = 0; nj < 8; nj++) {
                int col = cbase + nj * 8;
                float v0 = (acc[mi][nj][h * 2 + 0] - mu) * rstd * lng[col] + lnb[col];
                float v1 = (acc[mi][nj][h * 2 + 1] - mu) * rstd * lng[col + 1] + lnb[col + 1];
                *(float2*)(outf + (size_t)r * 128 + col) = make_float2(v0, v1);
            }
        }
    }
}

// ---------------- exclusive scan of counts (4096), 1 block -----------------
__global__ void k_scan() {
    __shared__ int wsum[32];
    const int t = threadIdx.x;
    int v[4];
    #pragma unroll
    for (int i = 0; i < 4; i++) v[i] = g_counts[t * 4 + i];
    int sum = v[0] + v[1] + v[2] + v[3];
    const int lane = t & 31, w = t >> 5;
    int sc = sum;
    #pragma unroll
    for (int o = 1; o < 32; o <<= 1) {
        int n = __shfl_up_sync(FULLM, sc, o);
        if (lane >= o) sc += n;
    }
    if (lane == 31) wsum[w] = sc;
    __syncthreads();
    if (w == 0) {
        int ws = wsum[lane];
        #pragma unroll
        for (int o = 1; o < 32; o <<= 1) {
            int n = __shfl_up_sync(FULLM, ws, o);
            if (lane >= o) ws += n;
        }
        wsum[lane] = ws;
    }
    __syncthreads();
    int base = (w > 0 ? wsum[w - 1] : 0) + sc - sum;
    #pragma unroll
    for (int i = 0; i < 4; i++) { g_offsets[t * 4 + i] = base; base += v[i]; }
}

// ---------------- bucket scatter --------------------------------------------
__global__ void k_scatter(const int* __restrict__ idx) {
    int r = blockIdx.x * blockDim.x + threadIdx.x;
    if (r < BN) {
        int a = idx[r];
        int p = atomicAdd(&g_cursor[a], 1);
        g_bucket[g_offsets[a] + p] = r;
    }
}

// ---------------- paired warp reduction --------------------------------------
__device__ __forceinline__ float pairred(float a0, float a1, int lane) {
    float x = (lane < 16) ? a1 : a0;
    x = __shfl_xor_sync(FULLM, x, 16);
    float t = ((lane < 16) ? a0 : a1) + x;
    t += __shfl_xor_sync(FULLM, t, 8);
    t += __shfl_xor_sync(FULLM, t, 4);
    t += __shfl_xor_sync(FULLM, t, 2);
    t += __shfl_xor_sync(FULLM, t, 1);
    return t;
}

// ---------------- fused attention: TWO rows per warp -------------------------
// 8 dot-sums per slot-pair reduced with 9 SHFLs; lane's value index:
// slot=b4 (lane&16), query=b3 (lane&8), row=b2 (lane&4). One exp per thread.
__global__ void __launch_bounds__(256)
k_attn(const int* __restrict__ idx,
       const float* __restrict__ wq, const float* __restrict__ Wg,
       const float* __restrict__ bg)
{
    const int t = threadIdx.x, lane = t & 31;
    const int r0 = blockIdx.x * 16 + (t >> 5) * 2;
    const int r1 = r0 + 1;
    const int a0 = idx[r0], a1 = idx[r1];

    float4 qr0 = h4_to_f4(*(const uint2*)(g_pqr + (size_t)r0 * 128 + lane * 4));
    float4 qw0 = h4_to_f4(*(const uint2*)(g_pqw + (size_t)r0 * 128 + lane * 4));
    float4 qr1 = h4_to_f4(*(const uint2*)(g_pqr + (size_t)r1 * 128 + lane * 4));
    float4 qw1 = h4_to_f4(*(const uint2*)(g_pqw + (size_t)r1 * 128 + lane * 4));

    // query norms: 4 sums via fold tree (b4=query, b3=row)
    {
        float p0 = qr0.x*qr0.x + qr0.y*qr0.y + qr0.z*qr0.z + qr0.w*qr0.w;
        float p1 = qw0.x*qw0.x + qw0.y*qw0.y + qw0.z*qw0.z + qw0.w*qw0.w;
        float p2 = qr1.x*qr1.x + qr1.y*qr1.y + qr1.z*qr1.z + qr1.w*qr1.w;
        float p3 = qw1.x*qw1.x + qw1.y*qw1.y + qw1.z*qw1.z + qw1.w*qw1.w;
        float X = ffold(p0, p1, 16, lane);
        float Y = ffold(p2, p3, 16, lane);
        float Z = ffold(X, Y, 8, lane);
        Z += __shfl_xor_sync(FULLM, Z, 4);
        Z += __shfl_xor_sync(FULLM, Z, 2);
        Z += __shfl_xor_sync(FULLM, Z, 1);
        float nr0v = __shfl_sync(FULLM, Z, 0);
        float nw0v = __shfl_sync(FULLM, Z, 16);
        float nr1v = __shfl_sync(FULLM, Z, 8);
        float nw1v = __shfl_sync(FULLM, Z, 24);
        // stash in qr0.x-adjacent registers via locals below
        float nq = (lane & 8) ? ((lane & 4) ? nw1v : nw0v)
                              : ((lane & 4) ? nr1v : nr0v);
        // lane_inv used in loop
        qr0.x = qr0.x; // no-op to keep structure
        // store to variable
        __shared__ float dummy; (void)dummy;
        // compute below
        float li = 1.f / fmaxf(sqrtf(nq), EPSN);
        // carry via static local
        // (fallthrough: declare lane_inv after block)
        #define LANE_INV li
        // intensity for both rows
        float4 gv = *(const float4*)(Wg + lane * 4);
        float4 x0 = *(const float4*)(wq + (size_t)r0 * 128 + lane * 4);
        float4 x1 = *(const float4*)(wq + (size_t)r1 * 128 + lane * 4);
        float i0 = x0.x*gv.x + x0.y*gv.y + x0.z*gv.z + x0.w*gv.w;
        float i1 = x1.x*gv.x + x1.y*gv.y + x1.z*gv.z + x1.w*gv.w;
        float pp = pairred(i0, i1, lane);
        float bg0 = bg[0];
        if (lane == 0)  g_inten[r0] = 1.f / (1.f + __expf(-(pp + bg0)));
        if (lane == 16) g_inten[r1] = 1.f / (1.f + __expf(-(pp + bg0)));

        float rmn0 = g_rmn[a0 * 16 + (lane & 15)];
        float rmn1 = g_rmn[a1 * 16 + (lane & 15)];

        float ax0=0.f, ay0=0.f, az0=0.f, aw0=0.f, lr0=0.f, lw0=0.f, myw0=0.f;
        float ax1=0.f, ay1=0.f, az1=0.f, aw1=0.f, lr1=0.f, lw1=0.f, myw1=0.f;
        const __half* mr0 = g_memh + (size_t)a0 * 2048;
        const __half* mr1 = g_memh + (size_t)a1 * 2048;

        #pragma unroll
        for (int j = 0; j < 8; j++) {
            const int s0 = 2 * j, s1 = 2 * j + 1;
            float4 f00 = h4_to_f4(*(const uint2*)(mr0 + s0 * 128 + lane * 4));
            float4 f10 = h4_to_f4(*(const uint2*)(mr0 + s1 * 128 + lane * 4));
            float4 f01 = h4_to_f4(*(const uint2*)(mr1 + s0 * 128 + lane * 4));
            float4 f11 = h4_to_f4(*(const uint2*)(mr1 + s1 * 128 + lane * 4));
            float v0 = f00.x*qr0.x + f00.y*qr0.y + f00.z*qr0.z + f00.w*qr0.w;
            float v1 = f10.x*qr0.x + f10.y*qr0.y + f10.z*qr0.z + f10.w*qr0.w;
            float v2 = f00.x*qw0.x + f00.y*qw0.y + f00.z*qw0.z + f00.w*qw0.w;
            float v3 = f10.x*qw0.x + f10.y*qw0.y + f10.z*qw0.z + f10.w*qw0.w;
            float v4 = f01.x*qr1.x + f01.y*qr1.y + f01.z*qr1.z + f01.w*qr1.w;
            float v5 = f11.x*qr1.x + f11.y*qr1.y + f11.z*qr1.z + f11.w*qr1.w;
            float v6 = f01.x*qw1.x + f01.y*qw1.y + f01.z*qw1.z + f01.w*qw1.w;
            float v7 = f11.x*qw1.x + f11.y*qw1.y + f11.z*qw1.z + f11.w*qw1.w;

            float A = ffold(v0, v1, 16, lane);   // b4 = slot
            float B = ffold(v2, v3, 16, lane);
            float Cc = ffold(v4, v5, 16, lane);
            float D = ffold(v6, v7, 16, lane);
            float E = ffold(A, B, 8, lane);      // b3 = query
            float F = ffold(Cc, D, 8, lane);
            float G = ffold(E, F, 4, lane);      // b2 = row
            G += __shfl_xor_sync(FULLM, G, 2);
            G += __shfl_xor_sync(FULLM, G, 1);

            int slotsel = s0 + ((lane >> 4) & 1);
            float ra = __shfl_sync(FULLM, rmn0, slotsel);
            float rb = __shfl_sync(FULLM, rmn1, slotsel);
            float rl = (lane & 4) ? rb : ra;
            float e = __expf(G * LANE_INV * rl);

            float er0 = __shfl_sync(FULLM, e, 0);    // row0 qr s0
            float ew0 = __shfl_sync(FULLM, e, 8);    // row0 qw s0
            float er1 = __shfl_sync(FULLM, e, 16);   // row0 qr s1
            float ew1 = __shfl_sync(FULLM, e, 24);   // row0 qw s1
            float er0b = __shfl_sync(FULLM, e, 4);   // row1 qr s0
            float ew0b = __shfl_sync(FULLM, e, 12);  // row1 qw s0
            float er1b = __shfl_sync(FULLM, e, 20);  // row1 qr s1
            float ew1b = __shfl_sync(FULLM, e, 28);  // row1 qw s1

            lr0 += er0 + er1; lw0 += ew0 + ew1;
            lr1 += er0b + er1b; lw1 += ew0b + ew1b;
            ax0 = fmaf(er0, f00.x, fmaf(er1, f10.x, ax0));
            ay0 = fmaf(er0, f00.y, fmaf(er1, f10.y, ay0));
            az0 = fmaf(er0, f00.z, fmaf(er1, f10.z, az0));
            aw0 = fmaf(er0, f00.w, fmaf(er1, f10.w, aw0));
            ax1 = fmaf(er0b, f01.x, fmaf(er1b, f11.x, ax1));
            ay1 = fmaf(er0b, f01.y, fmaf(er1b, f11.y, ay1));
            az1 = fmaf(er0b, f01.z, fmaf(er1b, f11.z, az1));
            aw1 = fmaf(er0b, f01.w, fmaf(er1b, f11.w, aw1));
            if (lane == s0) { myw0 = ew0; myw1 = ew0b; }
            if (lane == s1) { myw0 = ew1; myw1 = ew1b; }
        }
        float il0 = 1.f / lr0, il1 = 1.f / lr1;
        {
            __half2 h0 = __floats2half2_rn(ax0 * il0, ay0 * il0);
            __half2 h1 = __floats2half2_rn(az0 * il0, aw0 * il0);
            uint2 u; u.x = *(uint32_t*)&h0; u.y = *(uint32_t*)&h1;
            *(uint2*)(g_read + (size_t)r0 * 128 + lane * 4) = u;
        }
        {
            __half2 h0 = __floats2half2_rn(ax1 * il1, ay1 * il1);
            __half2 h1 = __floats2half2_rn(az1 * il1, aw1 * il1);
            uint2 u; u.x = *(uint32_t*)&h0; u.y = *(uint32_t*)&h1;
            *(uint2*)(g_read + (size_t)r1 * 128 + lane * 4) = u;
        }
        if (lane < 16) {
            g_ww[r0 * 16 + lane] = myw0 / lw0;
            g_ww[r1 * 16 + lane] = myw1 / lw1;
        }
        #undef LANE_INV
    }
}

// ---------------- per-agent gather-reduce + memory update + l2norm ---------
__global__ void k_agent(const float* __restrict__ mem, float* __restrict__ outm)
{
    __shared__ float part[8][8];
    __shared__ float nsh[16];
    __shared__ int rsh[256];
    const int a = blockIdx.x;
    const int t = threadIdx.x;
    const int d = t & 127;
    const int sg = t >> 7;
    const float* mrow = mem + (size_t)a * 2048;
    float* orow = outm + (size_t)a * 2048;
    const int cnt = g_counts[a];
    if (cnt == 0) {
        #pragma unroll
        for (int k = 0; k < 8; k++)
            orow[(sg * 8 + k) * 128 + d] = mrow[(sg * 8 + k) * 128 + d];
        return;
    }
    const int base = g_offsets[a];
    float E[8], A[8];
    #pragma unroll
    for (int k = 0; k < 8; k++) { E[k] = 0.f; A[k] = 0.f; }

    for (int cb = 0; cb < cnt; cb += 256) {
        int n = min(256, cnt - cb);
        if (t < n) rsh[t] = g_bucket[base + cb + t];   // stage row ids
        __syncthreads();
        for (int i = 0; i < n; i++) {
            int r = rsh[i];
            float eld = __half2float(g_el[(size_t)r * 128 + d]);
            float ald = __half2float(g_al[(size_t)r * 128 + d]);
            float itn = g_inten[r];
            float4 w0 = *(const float4*)(g_ww + r * 16 + sg * 8);
            float4 w1 = *(const float4*)(g_ww + r * 16 + sg * 8 + 4);
            float ei = itn / (1.f + __expf(-eld));
            float ai = itn * (1.f - 2.f / (__expf(2.f * ald) + 1.f));
            E[0] = fmaf(w0.x, ei, E[0]); A[0] = fmaf(w0.x, ai, A[0]);
            E[1] = fmaf(w0.y, ei, E[1]); A[1] = fmaf(w0.y, ai, A[1]);
            E[2] = fmaf(w0.z, ei, E[2]); A[2] = fmaf(w0.z, ai, A[2]);
            E[3] = fmaf(w0.w, ei, E[3]); A[3] = fmaf(w0.w, ai, A[3]);
            E[4] = fmaf(w1.x, ei, E[4]); A[4] = fmaf(w1.x, ai, A[4]);
            E[5] = fmaf(w1.y, ei, E[5]); A[5] = fmaf(w1.y, ai, A[5]);
            E[6] = fmaf(w1.z, ei, E[6]); A[6] = fmaf(w1.z, ai, A[6]);
            E[7] = fmaf(w1.w, ei, E[7]); A[7] = fmaf(w1.w, ai, A[7]);
        }
        __syncthreads();
    }

    float nv[8], p2[8];
    #pragma unroll
    for (int k = 0; k < 8; k++) {
        float m = mrow[(sg * 8 + k) * 128 + d];
        nv[k] = m * (1.f - E[k]) + A[k];
        p2[k] = nv[k] * nv[k];
    }
    #pragma unroll
    for (int o = 16; o > 0; o >>= 1) {
        #pragma unroll
        for (int k = 0; k < 8; k++) p2[k] += __shfl_xor_sync(FULLM, p2[k], o);
    }
    const int wp = t >> 5, lane = t & 31;
    if (lane == 0) {
        #pragma unroll
        for (int k = 0; k < 8; k++) part[wp][k] = p2[k];
    }
    __syncthreads();
    if (t < 16) {
        float n2 = part[(t >> 3) * 4 + 0][t & 7] + part[(t >> 3) * 4 + 1][t & 7]
                 + part[(t >> 3) * 4 + 2][t & 7] + part[(t >> 3) * 4 + 3][t & 7];
        nsh[t] = fmaxf(sqrtf(n2), EPSN);
    }
    __syncthreads();
    #pragma unroll
    for (int k = 0; k < 8; k++)
        orow[(sg * 8 + k) * 128 + d] = nv[k] / nsh[sg * 8 + k];
}

// ---------------- launch: fork-join graph ------------------------------------
//   main: (e0) gemmA (e1) -> [wait em] attn (e3) -> [wait e2b] agent -> [wait e4]
//   s2:   [wait e0] zero -> hist -> scan -> scatter -> [wait e1] gemmB (e2b)
//   s3:   [wait e0] mnorm (em) ... [wait e3] fuse (e4)
extern "C" void kernel_launch(void* const* d_in, const int* in_sizes, int n_in,
                              void* d_out, int out_size)
{
    const float* queries  = (const float*)d_in[0];
    const float* wqueries = (const float*)d_in[1];
    const float* memory   = (const float*)d_in[2];
    const float* Wq  = (const float*)d_in[3];
    const float* bq  = (const float*)d_in[4];
    const float* We  = (const float*)d_in[5];
    const float* be  = (const float*)d_in[6];
    const float* Wa  = (const float*)d_in[7];
    const float* ba  = (const float*)d_in[8];
    const float* Wf  = (const float*)d_in[9];
    const float* bf  = (const float*)d_in[10];
    const float* lng = (const float*)d_in[11];
    const float* lnb = (const float*)d_in[12];
    const float* Wg  = (const float*)d_in[13];
    const float* bg  = (const float*)d_in[14];
    const int*   idx = (const int*)d_in[15];

    float* outf = (float*)d_out;                 // fused_read [B,128]
    float* outm = outf + (size_t)BN * DD;        // new_memory [4096,16,128]

    const int gemm_smem = 2 * 128 * LDH * 2;     // 69632 bytes

    static cudaStream_t s2 = nullptr, s3 = nullptr;
    static cudaEvent_t e0, e1, em, e2b, e3, e4;
    if (s2 == nullptr) {
        cudaStreamCreateWithFlags(&s2, cudaStreamNonBlocking);
        cudaStreamCreateWithFlags(&s3, cudaStreamNonBlocking);
        cudaEventCreateWithFlags(&e0,  cudaEventDisableTiming);
        cudaEventCreateWithFlags(&e1,  cudaEventDisableTiming);
        cudaEventCreateWithFlags(&em,  cudaEventDisableTiming);
        cudaEventCreateWithFlags(&e2b, cudaEventDisableTiming);
        cudaEventCreateWithFlags(&e3,  cudaEventDisableTiming);
        cudaEventCreateWithFlags(&e4,  cudaEventDisableTiming);
        cudaFuncSetAttribute(k_gemm_h, cudaFuncAttributeMaxDynamicSharedMemorySize, gemm_smem);
        cudaFuncSetAttribute(k_fuse_h, cudaFuncAttributeMaxDynamicSharedMemorySize, gemm_smem);
    }

    // fork point (legal capture fork)
    cudaEventRecord(e0, (cudaStream_t)0);

    // side chain A: bucket construction
    cudaStreamWaitEvent(s2, e0, 0);
    k_zero<<<16, 256, 0, s2>>>();
    k_hist<<<BN / 256, 256, 0, s2>>>(idx);
    k_scan<<<1, 1024, 0, s2>>>();
    k_scatter<<<BN / 256, 256, 0, s2>>>(idx);

    // side chain B: fp16 memory mirror + slot norms (attn-only inputs)
    cudaStreamWaitEvent(s3, e0, 0);
    k_mnorm<<<NA * NS / 8, 256, 0, s3>>>(memory);
    cudaEventRecord(em, s3);

    // main: attention projections
    k_gemm_h<<<dim3(BN / 128, 2), 256, gemm_smem>>>(
        queries, wqueries, Wq, bq, We, be, Wa, ba, 0);             // pqr, pqw
    cudaEventRecord(e1, (cudaStream_t)0);

    // side A: erase/add projections (needed only by k_agent)
    cudaStreamWaitEvent(s2, e1, 0);
    k_gemm_h<<<dim3(BN / 128, 2), 256, gemm_smem, s2>>>(
        queries, wqueries, Wq, bq, We, be, Wa, ba, 2);             // el, al
    cudaEventRecord(e2b, s2);

    // main: attention (needs gemmA + mnorm)
    cudaStreamWaitEvent((cudaStream_t)0, em, 0);
    k_attn<<<BN / 16, 256>>>(idx, wqueries, Wg, bg);
    cudaEventRecord(e3, (cudaStream_t)0);

    // side B: fuse (overlaps agent)
    cudaStreamWaitEvent(s3, e3, 0);
    k_fuse_h<<<BN / 128, 256, gemm_smem, s3>>>(Wf, bf, lng, lnb, outf);
    cudaEventRecord(e4, s3);

    // main: memory update
    cudaStreamWaitEvent((cudaStream_t)0, e2b, 0);
    k_agent<<<NA, 256>>>(memory, outm);
    cudaStreamWaitEvent((cudaStream_t)0, e4, 0);
}